// round 5
// baseline (speedup 1.0000x reference)
#include <cuda_runtime.h>
#include <math.h>

#define TT 8
#define SS 14
#define LL 196            // S*S
#define NB 8
#define CC 1024
#define NH 16
#define HD 64
#define NTOK (1 + LL*TT)  // 1569
#define ROWS (NTOK*NB)    // 12552
#define PROWS (LL*TT*NB)  // 12544 patch rows
#define LS (LL + 1)       // 197 spatial seq
#define SB (TT*NB)        // 64 spatial batch
#define SROWS (LS*SB)     // 12608

// ---------------- scratch (device globals; no allocations) ----------------
__device__ float g_XBUF[(size_t)ROWS * CC];        // residual stream (post-conv x)
__device__ float g_LN  [(size_t)SROWS * CC];       // layernorm output (max rows)
__device__ float g_QKV [(size_t)SROWS * 3 * CC];   // qkv
__device__ float g_ATT [(size_t)SROWS * CC];       // attention output (pre-proj)
__device__ float g_PROJ[(size_t)SROWS * CC];       // spatial proj output
__device__ float g_H   [(size_t)ROWS * 4 * CC];    // xt_full (front PROWS*CC) then MLP hidden

// ---------------- Stage 1: depthwise 3x3x3 conv positional embedding ------
__global__ void pos_embed_kernel(const float* __restrict__ x,
                                 const float* __restrict__ pw,
                                 const float* __restrict__ pb) {
    int token = blockIdx.x;           // 0..1568
    int n = blockIdx.y;
    int tid = threadIdx.x;            // 256
    if (token == 0) {
        for (int c = tid; c < CC; c += 256)
            g_XBUF[(size_t)n * CC + c] = x[(size_t)n * CC + c];
        return;
    }
    int p = token - 1;
    int l = p / TT, t = p % TT;
    int i = l / SS, j = l % SS;
    const float* xb = x + ((size_t)token * NB + n) * CC;
    for (int c = tid; c < CC; c += 256) {
        float acc = pb[c];
        const float* w = pw + (size_t)c * 27;
        #pragma unroll
        for (int dt = 0; dt < 3; dt++) {
            int t2 = t + dt - 1;
            if ((unsigned)t2 >= TT) continue;
            #pragma unroll
            for (int di = 0; di < 3; di++) {
                int i2 = i + di - 1;
                if ((unsigned)i2 >= SS) continue;
                #pragma unroll
                for (int dj = 0; dj < 3; dj++) {
                    int j2 = j + dj - 1;
                    if ((unsigned)j2 >= SS) continue;
                    int np = (i2 * SS + j2) * TT + t2;
                    acc += w[dt*9 + di*3 + dj] *
                           x[((size_t)(1 + np) * NB + n) * CC + c];
                }
            }
        }
        g_XBUF[((size_t)token * NB + n) * CC + c] = xb[c] + acc;
    }
}

// ---------------- LayerNorm -------------------------------------------------
// mode 0: srcRow = row + srcOff (contiguous rows of src)
// mode 1: spatial gather — ls==0 reads cls row n from srcCls (post-conv x),
//         ls>=1 reads patch row ((ls-1)*TT+t)*NB+n from src (xt_full buffer)
__global__ void ln_kernel(const float* __restrict__ src,
                          const float* __restrict__ srcCls,
                          float* __restrict__ dst,
                          const float* __restrict__ g, const float* __restrict__ b,
                          int mode, int srcOff) {
    int row = blockIdx.x;
    const float* xr;
    if (mode == 0) {
        xr = src + (size_t)(row + srcOff) * CC;
    } else {
        int ls = row / SB, bb = row % SB;
        int t = bb / NB, n = bb % NB;
        if (ls == 0) xr = srcCls + (size_t)n * CC;
        else         xr = src + (size_t)(((ls - 1) * TT + t) * NB + n) * CC;
    }
    float* dr = dst + (size_t)row * CC;
    int tid = threadIdx.x;            // 256
    float s = 0.f, s2 = 0.f;
    float v[4];
    #pragma unroll
    for (int it = 0; it < 4; it++) {
        float val = xr[tid + it * 256];
        v[it] = val;
        s += val; s2 += val * val;
    }
    __shared__ float red[2][8];
    for (int m = 16; m; m >>= 1) {
        s  += __shfl_xor_sync(~0u, s, m);
        s2 += __shfl_xor_sync(~0u, s2, m);
    }
    if ((tid & 31) == 0) { red[0][tid >> 5] = s; red[1][tid >> 5] = s2; }
    __syncthreads();
    s = 0.f; s2 = 0.f;
    #pragma unroll
    for (int w = 0; w < 8; w++) { s += red[0][w]; s2 += red[1][w]; }
    float mean = s * (1.f / CC);
    float var  = s2 * (1.f / CC) - mean * mean;
    float inv  = rsqrtf(var + 1e-5f);
    #pragma unroll
    for (int it = 0; it < 4; it++) {
        int c = tid + it * 256;
        dr[c] = (v[it] - mean) * inv * g[c] + b[c];
    }
}

// ---------------- SGEMM: C[M,N] = A[M,K] @ W[N,K]^T + bias (+epilogue) -----
// MODE 0: store  MODE 1: QuickGELU  MODE 2: residual add (out = res + gemm)
template<int MODE>
__global__ void __launch_bounds__(256, 2)
sgemm_kernel(const float* __restrict__ A, const float* __restrict__ W,
             const float* __restrict__ bias, const float* __restrict__ res,
             float* __restrict__ out, int M, int N, int K) {
    __shared__ float As[8][128];
    __shared__ float Bs[8][128];
    int bm = blockIdx.y * 128, bn = blockIdx.x * 128;
    int tid = threadIdx.x;
    int lr = tid >> 1, lk = (tid & 1) << 2;
    int tm = (tid >> 4) << 3, tn = (tid & 15) << 3;
    float acc[8][8];
    #pragma unroll
    for (int i = 0; i < 8; i++)
        #pragma unroll
        for (int j = 0; j < 8; j++) acc[i][j] = 0.f;

    const float* Aptr = A + (size_t)(bm + lr) * K + lk;
    const float* Wptr = W + (size_t)(bn + lr) * K + lk;
    bool aval = (bm + lr) < M;

    for (int k0 = 0; k0 < K; k0 += 8) {
        float4 av = aval ? *(const float4*)(Aptr + k0) : make_float4(0.f,0.f,0.f,0.f);
        float4 wv = *(const float4*)(Wptr + k0);
        As[lk+0][lr] = av.x; As[lk+1][lr] = av.y; As[lk+2][lr] = av.z; As[lk+3][lr] = av.w;
        Bs[lk+0][lr] = wv.x; Bs[lk+1][lr] = wv.y; Bs[lk+2][lr] = wv.z; Bs[lk+3][lr] = wv.w;
        __syncthreads();
        #pragma unroll
        for (int kk = 0; kk < 8; kk++) {
            float4 a0 = *(const float4*)&As[kk][tm];
            float4 a1 = *(const float4*)&As[kk][tm + 4];
            float4 b0 = *(const float4*)&Bs[kk][tn];
            float4 b1 = *(const float4*)&Bs[kk][tn + 4];
            float ra[8] = {a0.x,a0.y,a0.z,a0.w,a1.x,a1.y,a1.z,a1.w};
            float rb[8] = {b0.x,b0.y,b0.z,b0.w,b1.x,b1.y,b1.z,b1.w};
            #pragma unroll
            for (int i = 0; i < 8; i++)
                #pragma unroll
                for (int j = 0; j < 8; j++)
                    acc[i][j] += ra[i] * rb[j];
        }
        __syncthreads();
    }
    #pragma unroll
    for (int i = 0; i < 8; i++) {
        int m = bm + tm + i;
        if (m < M) {
            size_t off = (size_t)m * N + bn + tn;
            #pragma unroll
            for (int j = 0; j < 8; j++) {
                float v2 = acc[i][j] + bias[bn + tn + j];
                if (MODE == 1) v2 = v2 / (1.f + expf(-1.702f * v2));
                if (MODE == 2) v2 += res[off + j];
                out[off + j] = v2;
            }
        }
    }
}

// ---------------- Temporal attention: batch (n,l), seq T=8 -----------------
__global__ void temporal_attn_kernel(const float* __restrict__ rpb_t) {
    int bid = blockIdx.x;             // 1568*16
    int h = bid & 15;
    int nl = bid >> 4;
    int n = nl & 7;
    int l = nl >> 3;
    __shared__ float Q[TT][HD + 1], K[TT][HD + 1], V[TT][HD + 1], P[TT][TT];
    int d = threadIdx.x;              // 64
    #pragma unroll
    for (int t = 0; t < TT; t++) {
        size_t r = (size_t)((l * TT + t) * NB + n);
        const float* q = g_QKV + r * 3072 + h * HD + d;
        Q[t][d] = q[0] * 0.125f;
        K[t][d] = q[1024];
        V[t][d] = q[2048];
    }
    __syncthreads();
    int tq = d >> 3, tk = d & 7;
    float s = rpb_t[(tq - tk + TT - 1) * NH + h];
    #pragma unroll
    for (int k = 0; k < HD; k++) s += Q[tq][k] * K[tk][k];
    float m = s;
    for (int msk = 4; msk; msk >>= 1) m = fmaxf(m, __shfl_xor_sync(~0u, m, msk));
    float p = expf(s - m);
    float sum = p;
    for (int msk = 4; msk; msk >>= 1) sum += __shfl_xor_sync(~0u, sum, msk);
    P[tq][tk] = p / sum;
    __syncthreads();
    #pragma unroll
    for (int t = 0; t < TT; t++) {
        float o = 0.f;
        #pragma unroll
        for (int k = 0; k < TT; k++) o += P[t][k] * V[k][d];
        g_ATT[((size_t)((l * TT + t) * NB + n)) * CC + h * HD + d] = o;
    }
}

// ---------------- Spatial attention: batch 64, heads 16, seq 197 -----------
// block = one (b,h); K,V resident in smem; loop over queries.
#define SPAT_SMEM_FLOATS (2 * LS * 65 + 64 + LS + 8 + 256)
__global__ void spatial_attn_kernel(const float* __restrict__ rpb_s) {
    extern __shared__ float sm[];
    float* Ks    = sm;                 // 197*65
    float* Vs    = Ks + LS * 65;       // 197*65
    float* Qrow  = Vs + LS * 65;       // 64
    float* S     = Qrow + 64;          // 197
    float* wred  = S + LS;             // 8
    float* Opart = wred + 8;           // 4*64
    int b = blockIdx.x >> 4;
    int h = blockIdx.x & 15;
    int tid = threadIdx.x;             // 256

    for (int idx = tid; idx < LS * HD; idx += 256) {
        int ls = idx >> 6, d2 = idx & 63;
        const float* q = g_QKV + ((size_t)(ls * SB + b)) * 3072 + h * HD + d2;
        Ks[ls * 65 + d2] = q[1024];
        Vs[ls * 65 + d2] = q[2048];
    }
    __syncthreads();

    for (int q = 0; q < LS; q++) {
        if (tid < HD)
            Qrow[tid] = g_QKV[((size_t)(q * SB + b)) * 3072 + h * HD + tid] * 0.125f;
        __syncthreads();
        float s = -1e30f;
        if (tid < LS) {
            s = 0.f;
            #pragma unroll 8
            for (int d2 = 0; d2 < HD; d2++) s += Qrow[d2] * Ks[tid * 65 + d2];
            if (q > 0 && tid > 0) {
                int lq = q - 1, lk = tid - 1;
                int idx = (lq / SS - lk / SS + SS - 1) * (2 * SS - 1)
                        + (lq % SS - lk % SS + SS - 1);
                s += rpb_s[idx * NH + h];
            }
        }
        float m = s;
        for (int msk = 16; msk; msk >>= 1) m = fmaxf(m, __shfl_xor_sync(~0u, m, msk));
        if ((tid & 31) == 0) wred[tid >> 5] = m;
        __syncthreads();
        float gm = wred[0];
        #pragma unroll
        for (int w = 1; w < 8; w++) gm = fmaxf(gm, wred[w]);
        float p = (tid < LS) ? expf(s - gm) : 0.f;
        if (tid < LS) S[tid] = p;
        float su = p;
        for (int msk = 16; msk; msk >>= 1) su += __shfl_xor_sync(~0u, su, msk);
        __syncthreads();                      // wred reads done; S visible
        if ((tid & 31) == 0) wred[tid >> 5] = su;
        __syncthreads();
        float gs = 0.f;
        #pragma unroll
        for (int w = 0; w < 8; w++) gs += wred[w];
        float inv = 1.f / gs;

        int d2 = tid & 63, chunk = tid >> 6;
        float o = 0.f;
        for (int k = chunk; k < LS; k += 4) o += S[k] * Vs[k * 65 + d2];
        Opart[chunk * 64 + d2] = o;
        __syncthreads();
        if (tid < HD) {
            float oo = (Opart[tid] + Opart[64 + tid] + Opart[128 + tid]
                      + Opart[192 + tid]) * inv;
            g_ATT[((size_t)(q * SB + b)) * CC + h * HD + tid] = oo;
        }
        __syncthreads();
    }
}

// ---------------- Spatial residual: scatter-add + cls mean -----------------
// Adds spatial proj output onto g_XBUF (which holds POST-CONV x; the temporal
// attention result is NOT part of the residual stream — it only feeds the
// spatial attention input, matching the reference dataflow).
__global__ void spatial_residual_kernel() {
    int row = blockIdx.x;             // 0..ROWS-1
    int token = row >> 3, n = row & 7;
    int tid = threadIdx.x;            // 256
    if (token == 0) {
        for (int c = tid; c < CC; c += 256) {
            float a = 0.f;
            #pragma unroll
            for (int t = 0; t < TT; t++)
                a += g_PROJ[((size_t)(t * NB + n)) * CC + c];
            g_XBUF[(size_t)row * CC + c] += a * 0.125f;
        }
    } else {
        int p = token - 1;
        int l = p >> 3, t = p & 7;    // p = l*TT + t
        size_t src = ((size_t)((l + 1) * SB + t * NB + n)) * CC;
        for (int c = tid; c < CC; c += 256)
            g_XBUF[(size_t)row * CC + c] += g_PROJ[src + c];
    }
}

// ---------------------------------------------------------------------------
extern "C" void kernel_launch(void* const* d_in, const int* in_sizes, int n_in,
                              void* d_out, int out_size) {
    const float* x      = (const float*)d_in[0];
    const float* pos_w  = (const float*)d_in[1];
    const float* pos_b  = (const float*)d_in[2];
    const float* ln_t_g = (const float*)d_in[3];
    const float* ln_t_b = (const float*)d_in[4];
    const float* rpb_t  = (const float*)d_in[5];
    const float* wqkv_t = (const float*)d_in[6];
    const float* bqkv_t = (const float*)d_in[7];
    const float* wo_t   = (const float*)d_in[8];
    const float* bo_t   = (const float*)d_in[9];
    const float* ln1_g  = (const float*)d_in[10];
    const float* ln1_b  = (const float*)d_in[11];
    const float* rpb_s  = (const float*)d_in[12];
    const float* wqkv_s = (const float*)d_in[13];
    const float* bqkv_s = (const float*)d_in[14];
    const float* wo_s   = (const float*)d_in[15];
    const float* bo_s   = (const float*)d_in[16];
    const float* ln2_g  = (const float*)d_in[17];
    const float* ln2_b  = (const float*)d_in[18];
    const float* fc_w   = (const float*)d_in[19];
    const float* fc_b   = (const float*)d_in[20];
    const float* proj_w = (const float*)d_in[21];
    const float* proj_b = (const float*)d_in[22];
    float* out = (float*)d_out;

    float *pX, *pLN, *pQKV, *pATT, *pPROJ, *pH;
    cudaGetSymbolAddress((void**)&pX,    g_XBUF);
    cudaGetSymbolAddress((void**)&pLN,   g_LN);
    cudaGetSymbolAddress((void**)&pQKV,  g_QKV);
    cudaGetSymbolAddress((void**)&pATT,  g_ATT);
    cudaGetSymbolAddress((void**)&pPROJ, g_PROJ);
    cudaGetSymbolAddress((void**)&pH,    g_H);

    int spatSmem = SPAT_SMEM_FLOATS * 4;
    cudaFuncSetAttribute(spatial_attn_kernel,
                         cudaFuncAttributeMaxDynamicSharedMemorySize, spatSmem);

    // Stage 1: positional conv embedding -> g_XBUF (residual stream)
    pos_embed_kernel<<<dim3(NTOK, NB), 256>>>(x, pos_w, pos_b);

    // Stage 2: temporal attention on patch rows.
    // xt_full = x[1:] + rt goes into pH — NOT back into the residual stream.
    ln_kernel<<<PROWS, 256>>>(pX, nullptr, pLN, ln_t_g, ln_t_b, 0, NB);
    sgemm_kernel<0><<<dim3(3072/128, PROWS/128), 256>>>(
        pLN, wqkv_t, bqkv_t, nullptr, pQKV, PROWS, 3072, 1024);
    temporal_attn_kernel<<<LL * NB * NH, 64>>>(rpb_t);
    sgemm_kernel<2><<<dim3(1024/128, PROWS/128), 256>>>(
        pATT, wo_t, bo_t, pX + (size_t)NB * CC, pH,
        PROWS, 1024, 1024);

    // Stage 3: spatial attention (seq 197 incl. cls).
    // LN input: cls row from post-conv x (pX), patch rows from xt_full (pH).
    ln_kernel<<<SROWS, 256>>>(pH, pX, pLN, ln1_g, ln1_b, 1, 0);
    sgemm_kernel<0><<<dim3(3072/128, (SROWS+127)/128), 256>>>(
        pLN, wqkv_s, bqkv_s, nullptr, pQKV, SROWS, 3072, 1024);
    spatial_attn_kernel<<<SB * NH, 256, spatSmem>>>(rpb_s);
    sgemm_kernel<0><<<dim3(1024/128, (SROWS+127)/128), 256>>>(
        pATT, wo_s, bo_s, nullptr, pPROJ, SROWS, 1024, 1024);
    spatial_residual_kernel<<<ROWS, 256>>>();   // adds onto post-conv x

    // Stage 4: MLP with QuickGELU (pH reused as hidden AFTER xt_full is dead)
    ln_kernel<<<ROWS, 256>>>(pX, nullptr, pLN, ln2_g, ln2_b, 0, 0);
    sgemm_kernel<1><<<dim3(4096/128, (ROWS+127)/128), 256>>>(
        pLN, fc_w, fc_b, nullptr, pH, ROWS, 4096, 1024);
    sgemm_kernel<2><<<dim3(1024/128, (ROWS+127)/128), 256>>>(
        pH, proj_w, proj_b, pX, out, ROWS, 1024, 4096);
}

// round 7
// speedup vs baseline: 1.5875x; 1.5875x over previous
#include <cuda_runtime.h>
#include <math.h>

#define TT 8
#define SS 14
#define LL 196            // S*S
#define NB 8
#define CC 1024
#define NH 16
#define HD 64
#define NTOK (1 + LL*TT)  // 1569
#define ROWS (NTOK*NB)    // 12552
#define PROWS (LL*TT*NB)  // 12544 patch rows
#define LS (LL + 1)       // 197 spatial seq
#define SB (TT*NB)        // 64 spatial batch
#define SROWS (LS*SB)     // 12608

// ---------------- scratch (device globals; no allocations) ----------------
__device__ float g_XBUF[(size_t)ROWS * CC];        // residual stream (post-conv x)
__device__ float g_LN  [(size_t)SROWS * CC];       // layernorm output (max rows)
__device__ float g_QKV [(size_t)SROWS * 3 * CC];   // qkv
__device__ float g_ATT [(size_t)SROWS * CC];       // attention output (pre-proj)
__device__ float g_PROJ[(size_t)SROWS * CC];       // spatial proj output
__device__ float g_H   [(size_t)ROWS * 4 * CC];    // xt_full (front) then MLP hidden

// ---------------- Stage 1: depthwise 3x3x3 conv positional embedding ------
__global__ void pos_embed_kernel(const float* __restrict__ x,
                                 const float* __restrict__ pw,
                                 const float* __restrict__ pb) {
    int token = blockIdx.x;           // 0..1568
    int n = blockIdx.y;
    int tid = threadIdx.x;            // 256
    if (token == 0) {
        for (int c = tid; c < CC; c += 256)
            g_XBUF[(size_t)n * CC + c] = x[(size_t)n * CC + c];
        return;
    }
    int p = token - 1;
    int l = p / TT, t = p % TT;
    int i = l / SS, j = l % SS;
    const float* xb = x + ((size_t)token * NB + n) * CC;
    for (int c = tid; c < CC; c += 256) {
        float acc = pb[c];
        const float* w = pw + (size_t)c * 27;
        #pragma unroll
        for (int dt = 0; dt < 3; dt++) {
            int t2 = t + dt - 1;
            if ((unsigned)t2 >= TT) continue;
            #pragma unroll
            for (int di = 0; di < 3; di++) {
                int i2 = i + di - 1;
                if ((unsigned)i2 >= SS) continue;
                #pragma unroll
                for (int dj = 0; dj < 3; dj++) {
                    int j2 = j + dj - 1;
                    if ((unsigned)j2 >= SS) continue;
                    int np = (i2 * SS + j2) * TT + t2;
                    acc += w[dt*9 + di*3 + dj] *
                           x[((size_t)(1 + np) * NB + n) * CC + c];
                }
            }
        }
        g_XBUF[((size_t)token * NB + n) * CC + c] = xb[c] + acc;
    }
}

// ---------------- LayerNorm -------------------------------------------------
__global__ void ln_kernel(const float* __restrict__ src,
                          const float* __restrict__ srcCls,
                          float* __restrict__ dst,
                          const float* __restrict__ g, const float* __restrict__ b,
                          int mode, int srcOff) {
    int row = blockIdx.x;
    const float* xr;
    if (mode == 0) {
        xr = src + (size_t)(row + srcOff) * CC;
    } else {
        int ls = row / SB, bb = row % SB;
        int t = bb / NB, n = bb % NB;
        if (ls == 0) xr = srcCls + (size_t)n * CC;
        else         xr = src + (size_t)(((ls - 1) * TT + t) * NB + n) * CC;
    }
    float* dr = dst + (size_t)row * CC;
    int tid = threadIdx.x;            // 256
    float s = 0.f, s2 = 0.f;
    float v[4];
    #pragma unroll
    for (int it = 0; it < 4; it++) {
        float val = xr[tid + it * 256];
        v[it] = val;
        s += val; s2 += val * val;
    }
    __shared__ float red[2][8];
    for (int m = 16; m; m >>= 1) {
        s  += __shfl_xor_sync(~0u, s, m);
        s2 += __shfl_xor_sync(~0u, s2, m);
    }
    if ((tid & 31) == 0) { red[0][tid >> 5] = s; red[1][tid >> 5] = s2; }
    __syncthreads();
    s = 0.f; s2 = 0.f;
    #pragma unroll
    for (int w = 0; w < 8; w++) { s += red[0][w]; s2 += red[1][w]; }
    float mean = s * (1.f / CC);
    float var  = s2 * (1.f / CC) - mean * mean;
    float inv  = rsqrtf(var + 1e-5f);
    #pragma unroll
    for (int it = 0; it < 4; it++) {
        int c = tid + it * 256;
        dr[c] = (v[it] - mean) * inv * g[c] + b[c];
    }
}

// ---------------- tf32 tensor-core GEMM ------------------------------------
// C[M,N] = A[M,K] @ W[N,K]^T + bias (+epilogue)
// MODE 0: store  MODE 1: QuickGELU  MODE 2: residual add (out = res + gemm)
// 128x128 tile, BK=16, 256 threads = 8 warps (2 m x 4 n), warp tile 64x32.
// mma.sync.m16n8k8 tf32, fp32 accumulate. ld-stride 136 -> conflict-free frags.

__device__ __forceinline__ unsigned f2tf32(float x) {
    unsigned u;
    asm("cvt.rna.tf32.f32 %0, %1;" : "=r"(u) : "f"(x));
    return u;
}

#define LDM 136

template<int MODE>
__global__ void __launch_bounds__(256, 1)
tgemm_kernel(const float* __restrict__ A, const float* __restrict__ W,
             const float* __restrict__ bias, const float* __restrict__ res,
             float* __restrict__ out, int M, int N, int K) {
    __shared__ unsigned As[2][16 * LDM];
    __shared__ unsigned Bs[2][16 * LDM];
    const int tid  = threadIdx.x;
    const int bm   = blockIdx.y * 128, bn = blockIdx.x * 128;
    const int lane = tid & 31, wid = tid >> 5;
    const int wm   = (wid & 1) << 6;       // 0 or 64
    const int wn   = (wid >> 1) << 5;      // 0,32,64,96
    const int lrow = tid >> 1;             // 0..127
    const int lk   = (tid & 1) << 2;       // 0 or 4

    float acc[16][4];
    #pragma unroll
    for (int i = 0; i < 16; i++)
        #pragma unroll
        for (int j = 0; j < 4; j++) acc[i][j] = 0.f;

    const bool aval = (bm + lrow) < M;
    const float* Aptr = A + (size_t)(bm + lrow) * K + lk;
    const float* Wptr = W + (size_t)(bn + lrow) * K + lk;

    const float4 z4 = make_float4(0.f, 0.f, 0.f, 0.f);
    float4 ra0, ra1, rb0, rb1;

    // preload slab 0
    ra0 = aval ? *(const float4*)(Aptr)     : z4;
    ra1 = aval ? *(const float4*)(Aptr + 8) : z4;
    rb0 = *(const float4*)(Wptr);
    rb1 = *(const float4*)(Wptr + 8);
    {
        unsigned* a = &As[0][0];
        a[(lk+0)*LDM + lrow] = f2tf32(ra0.x);
        a[(lk+1)*LDM + lrow] = f2tf32(ra0.y);
        a[(lk+2)*LDM + lrow] = f2tf32(ra0.z);
        a[(lk+3)*LDM + lrow] = f2tf32(ra0.w);
        a[(lk+8)*LDM + lrow] = f2tf32(ra1.x);
        a[(lk+9)*LDM + lrow] = f2tf32(ra1.y);
        a[(lk+10)*LDM + lrow] = f2tf32(ra1.z);
        a[(lk+11)*LDM + lrow] = f2tf32(ra1.w);
        unsigned* b = &Bs[0][0];
        b[(lk+0)*LDM + lrow] = f2tf32(rb0.x);
        b[(lk+1)*LDM + lrow] = f2tf32(rb0.y);
        b[(lk+2)*LDM + lrow] = f2tf32(rb0.z);
        b[(lk+3)*LDM + lrow] = f2tf32(rb0.w);
        b[(lk+8)*LDM + lrow] = f2tf32(rb1.x);
        b[(lk+9)*LDM + lrow] = f2tf32(rb1.y);
        b[(lk+10)*LDM + lrow] = f2tf32(rb1.z);
        b[(lk+11)*LDM + lrow] = f2tf32(rb1.w);
    }
    __syncthreads();

    const int NS = K >> 4;
    const int fc = lane & 3;      // k within 4 (frag col)
    const int fr = lane >> 2;     // 0..7 (frag row / n)

    for (int s = 0; s < NS; s++) {
        const int cur = s & 1;
        if (s + 1 < NS) {
            const float* ap = Aptr + (s + 1) * 16;
            const float* wp = Wptr + (s + 1) * 16;
            ra0 = aval ? *(const float4*)(ap)     : z4;
            ra1 = aval ? *(const float4*)(ap + 8) : z4;
            rb0 = *(const float4*)(wp);
            rb1 = *(const float4*)(wp + 8);
        }
        #pragma unroll
        for (int kk = 0; kk < 16; kk += 8) {
            unsigned af[4][4], bf[4][2];
            const unsigned* abase = &As[cur][(kk + fc) * LDM + wm + fr];
            #pragma unroll
            for (int mt = 0; mt < 4; mt++) {
                const unsigned* a = abase + mt * 16;
                af[mt][0] = a[0];
                af[mt][1] = a[8];
                af[mt][2] = a[4 * LDM];
                af[mt][3] = a[4 * LDM + 8];
            }
            const unsigned* bbase = &Bs[cur][(kk + fc) * LDM + wn + fr];
            #pragma unroll
            for (int nt = 0; nt < 4; nt++) {
                const unsigned* b = bbase + nt * 8;
                bf[nt][0] = b[0];
                bf[nt][1] = b[4 * LDM];
            }
            #pragma unroll
            for (int mt = 0; mt < 4; mt++)
                #pragma unroll
                for (int nt = 0; nt < 4; nt++) {
                    float* c = acc[mt * 4 + nt];
                    asm volatile(
                        "mma.sync.aligned.m16n8k8.row.col.f32.tf32.tf32.f32 "
                        "{%0,%1,%2,%3}, {%4,%5,%6,%7}, {%8,%9}, {%0,%1,%2,%3};\n"
                        : "+f"(c[0]), "+f"(c[1]), "+f"(c[2]), "+f"(c[3])
                        : "r"(af[mt][0]), "r"(af[mt][1]), "r"(af[mt][2]), "r"(af[mt][3]),
                          "r"(bf[nt][0]), "r"(bf[nt][1]));
                }
        }
        if (s + 1 < NS) {
            const int nxt = cur ^ 1;
            unsigned* a = &As[nxt][0];
            a[(lk+0)*LDM + lrow] = f2tf32(ra0.x);
            a[(lk+1)*LDM + lrow] = f2tf32(ra0.y);
            a[(lk+2)*LDM + lrow] = f2tf32(ra0.z);
            a[(lk+3)*LDM + lrow] = f2tf32(ra0.w);
            a[(lk+8)*LDM + lrow] = f2tf32(ra1.x);
            a[(lk+9)*LDM + lrow] = f2tf32(ra1.y);
            a[(lk+10)*LDM + lrow] = f2tf32(ra1.z);
            a[(lk+11)*LDM + lrow] = f2tf32(ra1.w);
            unsigned* b = &Bs[nxt][0];
            b[(lk+0)*LDM + lrow] = f2tf32(rb0.x);
            b[(lk+1)*LDM + lrow] = f2tf32(rb0.y);
            b[(lk+2)*LDM + lrow] = f2tf32(rb0.z);
            b[(lk+3)*LDM + lrow] = f2tf32(rb0.w);
            b[(lk+8)*LDM + lrow] = f2tf32(rb1.x);
            b[(lk+9)*LDM + lrow] = f2tf32(rb1.y);
            b[(lk+10)*LDM + lrow] = f2tf32(rb1.z);
            b[(lk+11)*LDM + lrow] = f2tf32(rb1.w);
        }
        __syncthreads();
    }

    // epilogue
    const int erow = lane >> 2;            // 0..7
    const int ecol = (lane & 3) * 2;       // 0,2,4,6
    #pragma unroll
    for (int mt = 0; mt < 4; mt++) {
        #pragma unroll
        for (int nt = 0; nt < 4; nt++) {
            const float* c = acc[mt * 4 + nt];
            int col = bn + wn + nt * 8 + ecol;
            float bv0 = bias[col], bv1 = bias[col + 1];
            #pragma unroll
            for (int half = 0; half < 2; half++) {
                int row = bm + wm + mt * 16 + erow + half * 8;
                if (row < M) {
                    size_t off = (size_t)row * N + col;
                    float v0 = c[half * 2 + 0] + bv0;
                    float v1 = c[half * 2 + 1] + bv1;
                    if (MODE == 1) {
                        v0 = v0 / (1.f + expf(-1.702f * v0));
                        v1 = v1 / (1.f + expf(-1.702f * v1));
                    }
                    if (MODE == 2) {
                        v0 += res[off];
                        v1 += res[off + 1];
                    }
                    out[off]     = v0;
                    out[off + 1] = v1;
                }
            }
        }
    }
}

// ---------------- Temporal attention: batch (n,l), seq T=8 -----------------
__global__ void temporal_attn_kernel(const float* __restrict__ rpb_t) {
    int bid = blockIdx.x;             // 1568*16
    int h = bid & 15;
    int nl = bid >> 4;
    int n = nl & 7;
    int l = nl >> 3;
    __shared__ float Q[TT][HD + 1], K[TT][HD + 1], V[TT][HD + 1], P[TT][TT];
    int d = threadIdx.x;              // 64
    #pragma unroll
    for (int t = 0; t < TT; t++) {
        size_t r = (size_t)((l * TT + t) * NB + n);
        const float* q = g_QKV + r * 3072 + h * HD + d;
        Q[t][d] = q[0] * 0.125f;
        K[t][d] = q[1024];
        V[t][d] = q[2048];
    }
    __syncthreads();
    int tq = d >> 3, tk = d & 7;
    float s = rpb_t[(tq - tk + TT - 1) * NH + h];
    #pragma unroll
    for (int k = 0; k < HD; k++) s += Q[tq][k] * K[tk][k];
    float m = s;
    for (int msk = 4; msk; msk >>= 1) m = fmaxf(m, __shfl_xor_sync(~0u, m, msk));
    float p = expf(s - m);
    float sum = p;
    for (int msk = 4; msk; msk >>= 1) sum += __shfl_xor_sync(~0u, sum, msk);
    P[tq][tk] = p / sum;
    __syncthreads();
    #pragma unroll
    for (int t = 0; t < TT; t++) {
        float o = 0.f;
        #pragma unroll
        for (int k = 0; k < TT; k++) o += P[t][k] * V[k][d];
        g_ATT[((size_t)((l * TT + t) * NB + n)) * CC + h * HD + d] = o;
    }
}

// ---------------- Spatial attention: batch 64, heads 16, seq 197 -----------
#define SPAT_SMEM_FLOATS (2 * LS * 65 + 64 + LS + 8 + 256)
__global__ void spatial_attn_kernel(const float* __restrict__ rpb_s) {
    extern __shared__ float sm[];
    float* Ks    = sm;                 // 197*65
    float* Vs    = Ks + LS * 65;       // 197*65
    float* Qrow  = Vs + LS * 65;       // 64
    float* S     = Qrow + 64;          // 197
    float* wred  = S + LS;             // 8
    float* Opart = wred + 8;           // 4*64
    int b = blockIdx.x >> 4;
    int h = blockIdx.x & 15;
    int tid = threadIdx.x;             // 256

    for (int idx = tid; idx < LS * HD; idx += 256) {
        int ls = idx >> 6, d2 = idx & 63;
        const float* q = g_QKV + ((size_t)(ls * SB + b)) * 3072 + h * HD + d2;
        Ks[ls * 65 + d2] = q[1024];
        Vs[ls * 65 + d2] = q[2048];
    }
    __syncthreads();

    for (int q = 0; q < LS; q++) {
        if (tid < HD)
            Qrow[tid] = g_QKV[((size_t)(q * SB + b)) * 3072 + h * HD + tid] * 0.125f;
        __syncthreads();
        float s = -1e30f;
        if (tid < LS) {
            s = 0.f;
            #pragma unroll 8
            for (int d2 = 0; d2 < HD; d2++) s += Qrow[d2] * Ks[tid * 65 + d2];
            if (q > 0 && tid > 0) {
                int lq = q - 1, lk = tid - 1;
                int idx = (lq / SS - lk / SS + SS - 1) * (2 * SS - 1)
                        + (lq % SS - lk % SS + SS - 1);
                s += rpb_s[idx * NH + h];
            }
        }
        float m = s;
        for (int msk = 16; msk; msk >>= 1) m = fmaxf(m, __shfl_xor_sync(~0u, m, msk));
        if ((tid & 31) == 0) wred[tid >> 5] = m;
        __syncthreads();
        float gm = wred[0];
        #pragma unroll
        for (int w = 1; w < 8; w++) gm = fmaxf(gm, wred[w]);
        float p = (tid < LS) ? expf(s - gm) : 0.f;
        if (tid < LS) S[tid] = p;
        float su = p;
        for (int msk = 16; msk; msk >>= 1) su += __shfl_xor_sync(~0u, su, msk);
        __syncthreads();
        if ((tid & 31) == 0) wred[tid >> 5] = su;
        __syncthreads();
        float gs = 0.f;
        #pragma unroll
        for (int w = 0; w < 8; w++) gs += wred[w];
        float inv = 1.f / gs;

        int d2 = tid & 63, chunk = tid >> 6;
        float o = 0.f;
        for (int k = chunk; k < LS; k += 4) o += S[k] * Vs[k * 65 + d2];
        Opart[chunk * 64 + d2] = o;
        __syncthreads();
        if (tid < HD) {
            float oo = (Opart[tid] + Opart[64 + tid] + Opart[128 + tid]
                      + Opart[192 + tid]) * inv;
            g_ATT[((size_t)(q * SB + b)) * CC + h * HD + tid] = oo;
        }
        __syncthreads();
    }
}

// ---------------- Spatial residual: scatter-add + cls mean -----------------
__global__ void spatial_residual_kernel() {
    int row = blockIdx.x;             // 0..ROWS-1
    int token = row >> 3, n = row & 7;
    int tid = threadIdx.x;            // 256
    if (token == 0) {
        for (int c = tid; c < CC; c += 256) {
            float a = 0.f;
            #pragma unroll
            for (int t = 0; t < TT; t++)
                a += g_PROJ[((size_t)(t * NB + n)) * CC + c];
            g_XBUF[(size_t)row * CC + c] += a * 0.125f;
        }
    } else {
        int p = token - 1;
        int l = p >> 3, t = p & 7;    // p = l*TT + t
        size_t src = ((size_t)((l + 1) * SB + t * NB + n)) * CC;
        for (int c = tid; c < CC; c += 256)
            g_XBUF[(size_t)row * CC + c] += g_PROJ[src + c];
    }
}

// ---------------------------------------------------------------------------
extern "C" void kernel_launch(void* const* d_in, const int* in_sizes, int n_in,
                              void* d_out, int out_size) {
    const float* x      = (const float*)d_in[0];
    const float* pos_w  = (const float*)d_in[1];
    const float* pos_b  = (const float*)d_in[2];
    const float* ln_t_g = (const float*)d_in[3];
    const float* ln_t_b = (const float*)d_in[4];
    const float* rpb_t  = (const float*)d_in[5];
    const float* wqkv_t = (const float*)d_in[6];
    const float* bqkv_t = (const float*)d_in[7];
    const float* wo_t   = (const float*)d_in[8];
    const float* bo_t   = (const float*)d_in[9];
    const float* ln1_g  = (const float*)d_in[10];
    const float* ln1_b  = (const float*)d_in[11];
    const float* rpb_s  = (const float*)d_in[12];
    const float* wqkv_s = (const float*)d_in[13];
    const float* bqkv_s = (const float*)d_in[14];
    const float* wo_s   = (const float*)d_in[15];
    const float* bo_s   = (const float*)d_in[16];
    const float* ln2_g  = (const float*)d_in[17];
    const float* ln2_b  = (const float*)d_in[18];
    const float* fc_w   = (const float*)d_in[19];
    const float* fc_b   = (const float*)d_in[20];
    const float* proj_w = (const float*)d_in[21];
    const float* proj_b = (const float*)d_in[22];
    float* out = (float*)d_out;

    float *pX, *pLN, *pQKV, *pATT, *pPROJ, *pH;
    cudaGetSymbolAddress((void**)&pX,    g_XBUF);
    cudaGetSymbolAddress((void**)&pLN,   g_LN);
    cudaGetSymbolAddress((void**)&pQKV,  g_QKV);
    cudaGetSymbolAddress((void**)&pATT,  g_ATT);
    cudaGetSymbolAddress((void**)&pPROJ, g_PROJ);
    cudaGetSymbolAddress((void**)&pH,    g_H);

    int spatSmem = SPAT_SMEM_FLOATS * 4;
    cudaFuncSetAttribute(spatial_attn_kernel,
                         cudaFuncAttributeMaxDynamicSharedMemorySize, spatSmem);

    // Stage 1: positional conv embedding -> g_XBUF (residual stream)
    pos_embed_kernel<<<dim3(NTOK, NB), 256>>>(x, pos_w, pos_b);

    // Stage 2: temporal attention on patch rows -> xt_full in pH
    ln_kernel<<<PROWS, 256>>>(pX, nullptr, pLN, ln_t_g, ln_t_b, 0, NB);
    tgemm_kernel<0><<<dim3(3072/128, PROWS/128), 256>>>(
        pLN, wqkv_t, bqkv_t, nullptr, pQKV, PROWS, 3072, 1024);
    temporal_attn_kernel<<<LL * NB * NH, 64>>>(rpb_t);
    tgemm_kernel<2><<<dim3(1024/128, PROWS/128), 256>>>(
        pATT, wo_t, bo_t, pX + (size_t)NB * CC, pH,
        PROWS, 1024, 1024);

    // Stage 3: spatial attention (seq 197 incl. cls)
    ln_kernel<<<SROWS, 256>>>(pH, pX, pLN, ln1_g, ln1_b, 1, 0);
    tgemm_kernel<0><<<dim3(3072/128, (SROWS+127)/128), 256>>>(
        pLN, wqkv_s, bqkv_s, nullptr, pQKV, SROWS, 3072, 1024);
    spatial_attn_kernel<<<SB * NH, 256, spatSmem>>>(rpb_s);
    tgemm_kernel<0><<<dim3(1024/128, (SROWS+127)/128), 256>>>(
        pATT, wo_s, bo_s, nullptr, pPROJ, SROWS, 1024, 1024);
    spatial_residual_kernel<<<ROWS, 256>>>();   // adds onto post-conv x

    // Stage 4: MLP with QuickGELU (pH reused as hidden AFTER xt_full is dead)
    ln_kernel<<<ROWS, 256>>>(pX, nullptr, pLN, ln2_g, ln2_b, 0, 0);
    tgemm_kernel<1><<<dim3(4096/128, (ROWS+127)/128), 256>>>(
        pLN, fc_w, fc_b, nullptr, pH, ROWS, 4096, 1024);
    tgemm_kernel<2><<<dim3(1024/128, (ROWS+127)/128), 256>>>(
        pH, proj_w, proj_b, pX, out, ROWS, 1024, 4096);
}

// round 8
// speedup vs baseline: 1.6871x; 1.0627x over previous
#include <cuda_runtime.h>
#include <math.h>

#define TT 8
#define SS 14
#define LL 196            // S*S
#define NB 8
#define CC 1024
#define NH 16
#define HD 64
#define NTOK (1 + LL*TT)  // 1569
#define ROWS (NTOK*NB)    // 12552
#define PROWS (LL*TT*NB)  // 12544 patch rows
#define LS (LL + 1)       // 197 spatial seq
#define SB (TT*NB)        // 64 spatial batch
#define SROWS (LS*SB)     // 12608

// ---------------- scratch (device globals; no allocations) ----------------
__device__ float g_XBUF[(size_t)ROWS * CC];        // residual stream (post-conv x)
__device__ float g_LN  [(size_t)SROWS * CC];       // layernorm output (tf32-rounded)
__device__ float g_QKV [(size_t)SROWS * 3 * CC];   // qkv (full fp32)
__device__ float g_ATT [(size_t)SROWS * CC];       // attention output (tf32-rounded)
__device__ float g_PROJ[(size_t)SROWS * CC];       // spatial proj output
__device__ float g_H   [(size_t)ROWS * 4 * CC];    // xt_full (front) then MLP hidden
__device__ float g_WT  [16777216];                 // tf32-rounded weights (16M floats)

__device__ __forceinline__ unsigned f2tf32(float x) {
    unsigned u;
    asm("cvt.rna.tf32.f32 %0, %1;" : "=r"(u) : "f"(x));
    return u;
}
__device__ __forceinline__ float rtf32(float x) {
    return __uint_as_float(f2tf32(x));
}

// ---------------- weight pre-round to tf32 bit patterns --------------------
__global__ void round_w_kernel(const float* __restrict__ s, float* __restrict__ d,
                               int n4) {
    int i = blockIdx.x * 256 + threadIdx.x;
    if (i < n4) {
        float4 v = ((const float4*)s)[i];
        v.x = rtf32(v.x); v.y = rtf32(v.y); v.z = rtf32(v.z); v.w = rtf32(v.w);
        ((float4*)d)[i] = v;
    }
}

// ---------------- Stage 1: depthwise 3x3x3 conv positional embedding ------
__global__ void pos_embed_kernel(const float* __restrict__ x,
                                 const float* __restrict__ pw,
                                 const float* __restrict__ pb) {
    int token = blockIdx.x;           // 0..1568
    int n = blockIdx.y;
    int tid = threadIdx.x;            // 256
    if (token == 0) {
        for (int c = tid; c < CC; c += 256)
            g_XBUF[(size_t)n * CC + c] = x[(size_t)n * CC + c];
        return;
    }
    int p = token - 1;
    int l = p / TT, t = p % TT;
    int i = l / SS, j = l % SS;
    const float* xb = x + ((size_t)token * NB + n) * CC;
    for (int c = tid; c < CC; c += 256) {
        float acc = pb[c];
        const float* w = pw + (size_t)c * 27;
        #pragma unroll
        for (int dt = 0; dt < 3; dt++) {
            int t2 = t + dt - 1;
            if ((unsigned)t2 >= TT) continue;
            #pragma unroll
            for (int di = 0; di < 3; di++) {
                int i2 = i + di - 1;
                if ((unsigned)i2 >= SS) continue;
                #pragma unroll
                for (int dj = 0; dj < 3; dj++) {
                    int j2 = j + dj - 1;
                    if ((unsigned)j2 >= SS) continue;
                    int np = (i2 * SS + j2) * TT + t2;
                    acc += w[dt*9 + di*3 + dj] *
                           x[((size_t)(1 + np) * NB + n) * CC + c];
                }
            }
        }
        g_XBUF[((size_t)token * NB + n) * CC + c] = xb[c] + acc;
    }
}

// ---------------- LayerNorm (output tf32-rounded: feeds GEMM A) ------------
__global__ void ln_kernel(const float* __restrict__ src,
                          const float* __restrict__ srcCls,
                          float* __restrict__ dst,
                          const float* __restrict__ g, const float* __restrict__ b,
                          int mode, int srcOff) {
    int row = blockIdx.x;
    const float* xr;
    if (mode == 0) {
        xr = src + (size_t)(row + srcOff) * CC;
    } else {
        int ls = row / SB, bb = row % SB;
        int t = bb / NB, n = bb % NB;
        if (ls == 0) xr = srcCls + (size_t)n * CC;
        else         xr = src + (size_t)(((ls - 1) * TT + t) * NB + n) * CC;
    }
    float* dr = dst + (size_t)row * CC;
    int tid = threadIdx.x;            // 256
    float s = 0.f, s2 = 0.f;
    float v[4];
    #pragma unroll
    for (int it = 0; it < 4; it++) {
        float val = xr[tid + it * 256];
        v[it] = val;
        s += val; s2 += val * val;
    }
    __shared__ float red[2][8];
    for (int m = 16; m; m >>= 1) {
        s  += __shfl_xor_sync(~0u, s, m);
        s2 += __shfl_xor_sync(~0u, s2, m);
    }
    if ((tid & 31) == 0) { red[0][tid >> 5] = s; red[1][tid >> 5] = s2; }
    __syncthreads();
    s = 0.f; s2 = 0.f;
    #pragma unroll
    for (int w = 0; w < 8; w++) { s += red[0][w]; s2 += red[1][w]; }
    float mean = s * (1.f / CC);
    float var  = s2 * (1.f / CC) - mean * mean;
    float inv  = rsqrtf(var + 1e-5f);
    #pragma unroll
    for (int it = 0; it < 4; it++) {
        int c = tid + it * 256;
        dr[c] = rtf32((v[it] - mean) * inv * g[c] + b[c]);
    }
}

// ---------------- tf32 tensor-core GEMM, cp.async 4-stage pipeline ---------
// C[M,N] = A[M,K] @ W[N,K]^T + bias (+epilogue)
// MODE 0: store  MODE 1: QuickGELU (tf32-rounded out)  MODE 2: residual add
// A and W must be pre-rounded to tf32 bit patterns.
// 128x128 tile, BK=16, 256 thr = 8 warps (2m x 4n), warp tile 64x32.
// smem rows [row][k], stride 20 floats -> conflict-free fragment gathers.

#define ASTRIDE 20
#define STAGEF  (2 * 128 * ASTRIDE)          // floats per stage (A+B)
#define GSTAGES 4
#define GSMEM_BYTES (GSTAGES * STAGEF * 4)   // 81920

template<int MODE>
__global__ void __launch_bounds__(256, 1)
tgemm_kernel(const float* __restrict__ A, const float* __restrict__ W,
             const float* __restrict__ bias, const float* __restrict__ res,
             float* __restrict__ out, int M, int N, int K) {
    extern __shared__ float sm[];
    const int tid  = threadIdx.x;
    const int bm   = blockIdx.y * 128, bn = blockIdx.x * 128;
    const int lane = tid & 31, wid = tid >> 5;
    const int wm   = (wid & 1) << 6;       // 0 or 64
    const int wn   = (wid >> 1) << 5;      // 0,32,64,96
    const int fr   = lane >> 2;            // 0..7
    const int fc   = lane & 3;             // 0..3

    // loader role: tid<128 loads A row tid, else W row tid-128
    const int  lrow  = tid & 127;
    const bool loadA = tid < 128;
    const bool valid = loadA ? ((bm + lrow) < M) : true;
    const int  vsz   = valid ? 16 : 0;
    int grow = loadA ? (bm + lrow) : (bn + lrow);
    if (loadA && !valid) grow = M - 1;     // clamped (never read: vsz=0)
    const float* gRow = (loadA ? A : W) + (size_t)grow * K;
    unsigned sbase = (unsigned)__cvta_generic_to_shared(sm);
    const unsigned dRowOff = ((loadA ? 0 : 128 * ASTRIDE) + lrow * ASTRIDE) * 4;

    float acc[16][4];
    #pragma unroll
    for (int i = 0; i < 16; i++)
        #pragma unroll
        for (int j = 0; j < 4; j++) acc[i][j] = 0.f;

    const int NS = K >> 4;

    // prefetch GSTAGES-1 slabs
    #pragma unroll
    for (int s = 0; s < GSTAGES - 1; s++) {
        unsigned d = sbase + (unsigned)(s * STAGEF * 4) + dRowOff;
        const float* gp = gRow + s * 16;
        #pragma unroll
        for (int c = 0; c < 4; c++)
            asm volatile("cp.async.cg.shared.global [%0], [%1], 16, %2;\n"
                         :: "r"(d + c * 16), "l"(gp + c * 4), "r"(vsz));
        asm volatile("cp.async.commit_group;\n");
    }

    for (int s = 0; s < NS; s++) {
        asm volatile("cp.async.wait_group %0;\n" :: "n"(GSTAGES - 2));
        __syncthreads();

        // issue loads for slab s+GSTAGES-1 (overlaps with mma below)
        if (s + GSTAGES - 1 < NS) {
            int st = (s + GSTAGES - 1) & (GSTAGES - 1);
            unsigned d = sbase + (unsigned)(st * STAGEF * 4) + dRowOff;
            const float* gp = gRow + (s + GSTAGES - 1) * 16;
            #pragma unroll
            for (int c = 0; c < 4; c++)
                asm volatile("cp.async.cg.shared.global [%0], [%1], 16, %2;\n"
                             :: "r"(d + c * 16), "l"(gp + c * 4), "r"(vsz));
        }
        asm volatile("cp.async.commit_group;\n");

        const float* smA = sm + (s & (GSTAGES - 1)) * STAGEF;
        const float* smB = smA + 128 * ASTRIDE;

        #pragma unroll
        for (int kk = 0; kk < 16; kk += 8) {
            unsigned af[4][4], bf[4][2];
            #pragma unroll
            for (int mt = 0; mt < 4; mt++) {
                const float* p = smA + (wm + mt * 16 + fr) * ASTRIDE + kk + fc;
                af[mt][0] = __float_as_uint(p[0]);
                af[mt][1] = __float_as_uint(p[8 * ASTRIDE]);
                af[mt][2] = __float_as_uint(p[4]);
                af[mt][3] = __float_as_uint(p[8 * ASTRIDE + 4]);
            }
            #pragma unroll
            for (int nt = 0; nt < 4; nt++) {
                const float* p = smB + (wn + nt * 8 + fr) * ASTRIDE + kk + fc;
                bf[nt][0] = __float_as_uint(p[0]);
                bf[nt][1] = __float_as_uint(p[4]);
            }
            #pragma unroll
            for (int mt = 0; mt < 4; mt++)
                #pragma unroll
                for (int nt = 0; nt < 4; nt++) {
                    float* c = acc[mt * 4 + nt];
                    asm volatile(
                        "mma.sync.aligned.m16n8k8.row.col.f32.tf32.tf32.f32 "
                        "{%0,%1,%2,%3}, {%4,%5,%6,%7}, {%8,%9}, {%0,%1,%2,%3};\n"
                        : "+f"(c[0]), "+f"(c[1]), "+f"(c[2]), "+f"(c[3])
                        : "r"(af[mt][0]), "r"(af[mt][1]), "r"(af[mt][2]), "r"(af[mt][3]),
                          "r"(bf[nt][0]), "r"(bf[nt][1]));
                }
        }
    }

    // epilogue
    const int erow = lane >> 2;            // 0..7
    const int ecol = (lane & 3) * 2;       // 0,2,4,6
    #pragma unroll
    for (int mt = 0; mt < 4; mt++) {
        #pragma unroll
        for (int nt = 0; nt < 4; nt++) {
            const float* c = acc[mt * 4 + nt];
            int col = bn + wn + nt * 8 + ecol;
            float bv0 = bias[col], bv1 = bias[col + 1];
            #pragma unroll
            for (int half = 0; half < 2; half++) {
                int row = bm + wm + mt * 16 + erow + half * 8;
                if (row < M) {
                    size_t off = (size_t)row * N + col;
                    float v0 = c[half * 2 + 0] + bv0;
                    float v1 = c[half * 2 + 1] + bv1;
                    if (MODE == 1) {
                        v0 = rtf32(v0 / (1.f + expf(-1.702f * v0)));
                        v1 = rtf32(v1 / (1.f + expf(-1.702f * v1)));
                    }
                    if (MODE == 2) {
                        v0 += res[off];
                        v1 += res[off + 1];
                    }
                    out[off]     = v0;
                    out[off + 1] = v1;
                }
            }
        }
    }
}

// ---------------- Temporal attention: batch (n,l), seq T=8 -----------------
__global__ void temporal_attn_kernel(const float* __restrict__ rpb_t) {
    int bid = blockIdx.x;             // 1568*16
    int h = bid & 15;
    int nl = bid >> 4;
    int n = nl & 7;
    int l = nl >> 3;
    __shared__ float Q[TT][HD + 1], K[TT][HD + 1], V[TT][HD + 1], P[TT][TT];
    int d = threadIdx.x;              // 64
    #pragma unroll
    for (int t = 0; t < TT; t++) {
        size_t r = (size_t)((l * TT + t) * NB + n);
        const float* q = g_QKV + r * 3072 + h * HD + d;
        Q[t][d] = q[0] * 0.125f;
        K[t][d] = q[1024];
        V[t][d] = q[2048];
    }
    __syncthreads();
    int tq = d >> 3, tk = d & 7;
    float s = rpb_t[(tq - tk + TT - 1) * NH + h];
    #pragma unroll
    for (int k = 0; k < HD; k++) s += Q[tq][k] * K[tk][k];
    float m = s;
    for (int msk = 4; msk; msk >>= 1) m = fmaxf(m, __shfl_xor_sync(~0u, m, msk));
    float p = expf(s - m);
    float sum = p;
    for (int msk = 4; msk; msk >>= 1) sum += __shfl_xor_sync(~0u, sum, msk);
    P[tq][tk] = p / sum;
    __syncthreads();
    #pragma unroll
    for (int t = 0; t < TT; t++) {
        float o = 0.f;
        #pragma unroll
        for (int k = 0; k < TT; k++) o += P[t][k] * V[k][d];
        g_ATT[((size_t)((l * TT + t) * NB + n)) * CC + h * HD + d] = rtf32(o);
    }
}

// ---------------- Spatial attention: batch 64, heads 16, seq 197 -----------
#define SPAT_SMEM_FLOATS (2 * LS * 65 + 64 + LS + 8 + 256)
__global__ void spatial_attn_kernel(const float* __restrict__ rpb_s) {
    extern __shared__ float sm[];
    float* Ks    = sm;                 // 197*65
    float* Vs    = Ks + LS * 65;       // 197*65
    float* Qrow  = Vs + LS * 65;       // 64
    float* S     = Qrow + 64;          // 197
    float* wred  = S + LS;             // 8
    float* Opart = wred + 8;           // 4*64
    int b = blockIdx.x >> 4;
    int h = blockIdx.x & 15;
    int tid = threadIdx.x;             // 256

    for (int idx = tid; idx < LS * HD; idx += 256) {
        int ls = idx >> 6, d2 = idx & 63;
        const float* q = g_QKV + ((size_t)(ls * SB + b)) * 3072 + h * HD + d2;
        Ks[ls * 65 + d2] = q[1024];
        Vs[ls * 65 + d2] = q[2048];
    }
    __syncthreads();

    for (int q = 0; q < LS; q++) {
        if (tid < HD)
            Qrow[tid] = g_QKV[((size_t)(q * SB + b)) * 3072 + h * HD + tid] * 0.125f;
        __syncthreads();
        float s = -1e30f;
        if (tid < LS) {
            s = 0.f;
            #pragma unroll 8
            for (int d2 = 0; d2 < HD; d2++) s += Qrow[d2] * Ks[tid * 65 + d2];
            if (q > 0 && tid > 0) {
                int lq = q - 1, lk = tid - 1;
                int idx = (lq / SS - lk / SS + SS - 1) * (2 * SS - 1)
                        + (lq % SS - lk % SS + SS - 1);
                s += rpb_s[idx * NH + h];
            }
        }
        float m = s;
        for (int msk = 16; msk; msk >>= 1) m = fmaxf(m, __shfl_xor_sync(~0u, m, msk));
        if ((tid & 31) == 0) wred[tid >> 5] = m;
        __syncthreads();
        float gm = wred[0];
        #pragma unroll
        for (int w = 1; w < 8; w++) gm = fmaxf(gm, wred[w]);
        float p = (tid < LS) ? expf(s - gm) : 0.f;
        if (tid < LS) S[tid] = p;
        float su = p;
        for (int msk = 16; msk; msk >>= 1) su += __shfl_xor_sync(~0u, su, msk);
        __syncthreads();
        if ((tid & 31) == 0) wred[tid >> 5] = su;
        __syncthreads();
        float gs = 0.f;
        #pragma unroll
        for (int w = 0; w < 8; w++) gs += wred[w];
        float inv = 1.f / gs;

        int d2 = tid & 63, chunk = tid >> 6;
        float o = 0.f;
        for (int k = chunk; k < LS; k += 4) o += S[k] * Vs[k * 65 + d2];
        Opart[chunk * 64 + d2] = o;
        __syncthreads();
        if (tid < HD) {
            float oo = (Opart[tid] + Opart[64 + tid] + Opart[128 + tid]
                      + Opart[192 + tid]) * inv;
            g_ATT[((size_t)(q * SB + b)) * CC + h * HD + tid] = rtf32(oo);
        }
        __syncthreads();
    }
}

// ---------------- Spatial residual: scatter-add + cls mean -----------------
__global__ void spatial_residual_kernel() {
    int row = blockIdx.x;             // 0..ROWS-1
    int token = row >> 3, n = row & 7;
    int tid = threadIdx.x;            // 256
    if (token == 0) {
        for (int c = tid; c < CC; c += 256) {
            float a = 0.f;
            #pragma unroll
            for (int t = 0; t < TT; t++)
                a += g_PROJ[((size_t)(t * NB + n)) * CC + c];
            g_XBUF[(size_t)row * CC + c] += a * 0.125f;
        }
    } else {
        int p = token - 1;
        int l = p >> 3, t = p & 7;    // p = l*TT + t
        size_t src = ((size_t)((l + 1) * SB + t * NB + n)) * CC;
        for (int c = tid; c < CC; c += 256)
            g_XBUF[(size_t)row * CC + c] += g_PROJ[src + c];
    }
}

// ---------------------------------------------------------------------------
extern "C" void kernel_launch(void* const* d_in, const int* in_sizes, int n_in,
                              void* d_out, int out_size) {
    const float* x      = (const float*)d_in[0];
    const float* pos_w  = (const float*)d_in[1];
    const float* pos_b  = (const float*)d_in[2];
    const float* ln_t_g = (const float*)d_in[3];
    const float* ln_t_b = (const float*)d_in[4];
    const float* rpb_t  = (const float*)d_in[5];
    const float* wqkv_t = (const float*)d_in[6];
    const float* bqkv_t = (const float*)d_in[7];
    const float* wo_t   = (const float*)d_in[8];
    const float* bo_t   = (const float*)d_in[9];
    const float* ln1_g  = (const float*)d_in[10];
    const float* ln1_b  = (const float*)d_in[11];
    const float* rpb_s  = (const float*)d_in[12];
    const float* wqkv_s = (const float*)d_in[13];
    const float* bqkv_s = (const float*)d_in[14];
    const float* wo_s   = (const float*)d_in[15];
    const float* bo_s   = (const float*)d_in[16];
    const float* ln2_g  = (const float*)d_in[17];
    const float* ln2_b  = (const float*)d_in[18];
    const float* fc_w   = (const float*)d_in[19];
    const float* fc_b   = (const float*)d_in[20];
    const float* proj_w = (const float*)d_in[21];
    const float* proj_b = (const float*)d_in[22];
    float* out = (float*)d_out;

    float *pX, *pLN, *pQKV, *pATT, *pPROJ, *pH, *pWT;
    cudaGetSymbolAddress((void**)&pX,    g_XBUF);
    cudaGetSymbolAddress((void**)&pLN,   g_LN);
    cudaGetSymbolAddress((void**)&pQKV,  g_QKV);
    cudaGetSymbolAddress((void**)&pATT,  g_ATT);
    cudaGetSymbolAddress((void**)&pPROJ, g_PROJ);
    cudaGetSymbolAddress((void**)&pH,    g_H);
    cudaGetSymbolAddress((void**)&pWT,   g_WT);

    int spatSmem = SPAT_SMEM_FLOATS * 4;
    cudaFuncSetAttribute(spatial_attn_kernel,
                         cudaFuncAttributeMaxDynamicSharedMemorySize, spatSmem);
    cudaFuncSetAttribute(tgemm_kernel<0>,
                         cudaFuncAttributeMaxDynamicSharedMemorySize, GSMEM_BYTES);
    cudaFuncSetAttribute(tgemm_kernel<1>,
                         cudaFuncAttributeMaxDynamicSharedMemorySize, GSMEM_BYTES);
    cudaFuncSetAttribute(tgemm_kernel<2>,
                         cudaFuncAttributeMaxDynamicSharedMemorySize, GSMEM_BYTES);

    // tf32-rounded weight copies (offsets in g_WT)
    float* wqkvT = pWT;                      // 3M
    float* woT   = pWT + 3145728;            // 1M
    float* wqkvS = pWT + 4194304;            // 3M
    float* woS   = pWT + 7340032;            // 1M
    float* fcW   = pWT + 8388608;            // 4M
    float* projW = pWT + 12582912;           // 4M
    round_w_kernel<<<(3145728/4+255)/256, 256>>>(wqkv_t, wqkvT, 3145728/4);
    round_w_kernel<<<(1048576/4+255)/256, 256>>>(wo_t,   woT,   1048576/4);
    round_w_kernel<<<(3145728/4+255)/256, 256>>>(wqkv_s, wqkvS, 3145728/4);
    round_w_kernel<<<(1048576/4+255)/256, 256>>>(wo_s,   woS,   1048576/4);
    round_w_kernel<<<(4194304/4+255)/256, 256>>>(fc_w,   fcW,   4194304/4);
    round_w_kernel<<<(4194304/4+255)/256, 256>>>(proj_w, projW, 4194304/4);

    // Stage 1: positional conv embedding -> g_XBUF (residual stream)
    pos_embed_kernel<<<dim3(NTOK, NB), 256>>>(x, pos_w, pos_b);

    // Stage 2: temporal attention on patch rows -> xt_full in pH
    ln_kernel<<<PROWS, 256>>>(pX, nullptr, pLN, ln_t_g, ln_t_b, 0, NB);
    tgemm_kernel<0><<<dim3(3072/128, PROWS/128), 256, GSMEM_BYTES>>>(
        pLN, wqkvT, bqkv_t, nullptr, pQKV, PROWS, 3072, 1024);
    temporal_attn_kernel<<<LL * NB * NH, 64>>>(rpb_t);
    tgemm_kernel<2><<<dim3(1024/128, PROWS/128), 256, GSMEM_BYTES>>>(
        pATT, woT, bo_t, pX + (size_t)NB * CC, pH,
        PROWS, 1024, 1024);

    // Stage 3: spatial attention (seq 197 incl. cls)
    ln_kernel<<<SROWS, 256>>>(pH, pX, pLN, ln1_g, ln1_b, 1, 0);
    tgemm_kernel<0><<<dim3(3072/128, (SROWS+127)/128), 256, GSMEM_BYTES>>>(
        pLN, wqkvS, bqkv_s, nullptr, pQKV, SROWS, 3072, 1024);
    spatial_attn_kernel<<<SB * NH, 256, spatSmem>>>(rpb_s);
    tgemm_kernel<0><<<dim3(1024/128, (SROWS+127)/128), 256, GSMEM_BYTES>>>(
        pATT, woS, bo_s, nullptr, pPROJ, SROWS, 1024, 1024);
    spatial_residual_kernel<<<ROWS, 256>>>();   // adds onto post-conv x

    // Stage 4: MLP with QuickGELU (pH reused as hidden AFTER xt_full is dead)
    ln_kernel<<<ROWS, 256>>>(pX, nullptr, pLN, ln2_g, ln2_b, 0, 0);
    tgemm_kernel<1><<<dim3(4096/128, (ROWS+127)/128), 256, GSMEM_BYTES>>>(
        pLN, fcW, fc_b, nullptr, pH, ROWS, 4096, 1024);
    tgemm_kernel<2><<<dim3(1024/128, (ROWS+127)/128), 256, GSMEM_BYTES>>>(
        pH, projW, proj_b, pX, out, ROWS, 1024, 4096);
}

// round 10
// speedup vs baseline: 2.6342x; 1.5614x over previous
#include <cuda_runtime.h>
#include <cuda_fp16.h>
#include <math.h>
#include <stdint.h>

#define TT 8
#define SS 14
#define LL 196            // S*S
#define NB 8
#define CC 1024
#define NH 16
#define HD 64
#define NTOK (1 + LL*TT)  // 1569
#define ROWS (NTOK*NB)    // 12552
#define PROWS (LL*TT*NB)  // 12544 patch rows
#define LS (LL + 1)       // 197 spatial seq
#define SB (TT*NB)        // 64 spatial batch
#define SROWS (LS*SB)     // 12608

// ---------------- scratch (device globals; no allocations) ----------------
__device__ __align__(256) float  g_XBUF[(size_t)ROWS * CC];      // residual stream
__device__ __align__(256) __half g_LNh [(size_t)SROWS * CC];     // LN out (fp16)
__device__ __align__(256) float  g_QKV [(size_t)SROWS * 3 * CC]; // qkv fp32
__device__ __align__(256) __half g_ATTh[(size_t)SROWS * CC];     // attn out (fp16)
__device__ __align__(256) float  g_PROJ[(size_t)SROWS * CC];     // spatial proj out
__device__ __align__(256) float  g_XT  [(size_t)PROWS * CC];     // xt_full fp32
__device__ __align__(256) __half g_Hh  [(size_t)ROWS * 4 * CC];  // MLP hidden (fp16)
__device__ __align__(256) __half g_WTh [16777216];               // fp16 weights

// ---------------- weight prep: fp32 -> fp16 --------------------------------
__global__ void wprep_kernel(const float* __restrict__ s, __half* __restrict__ d,
                             int n4) {
    int i = blockIdx.x * 256 + threadIdx.x;
    if (i < n4) {
        float4 v = ((const float4*)s)[i];
        __half2 lo = __floats2half2_rn(v.x, v.y);
        __half2 hi = __floats2half2_rn(v.z, v.w);
        ((__half2*)d)[i * 2]     = lo;
        ((__half2*)d)[i * 2 + 1] = hi;
    }
}

// ---------------- Stage 1: depthwise 3x3x3 conv positional embedding ------
__global__ void pos_embed_kernel(const float* __restrict__ x,
                                 const float* __restrict__ pw,
                                 const float* __restrict__ pb) {
    int token = blockIdx.x, n = blockIdx.y, tid = threadIdx.x;
    if (token == 0) {
        for (int c = tid; c < CC; c += 256)
            g_XBUF[(size_t)n * CC + c] = x[(size_t)n * CC + c];
        return;
    }
    int p = token - 1;
    int l = p / TT, t = p % TT;
    int i = l / SS, j = l % SS;
    const float* xb = x + ((size_t)token * NB + n) * CC;
    for (int c = tid; c < CC; c += 256) {
        float acc = pb[c];
        const float* w = pw + (size_t)c * 27;
        #pragma unroll
        for (int dt = 0; dt < 3; dt++) {
            int t2 = t + dt - 1;
            if ((unsigned)t2 >= TT) continue;
            #pragma unroll
            for (int di = 0; di < 3; di++) {
                int i2 = i + di - 1;
                if ((unsigned)i2 >= SS) continue;
                #pragma unroll
                for (int dj = 0; dj < 3; dj++) {
                    int j2 = j + dj - 1;
                    if ((unsigned)j2 >= SS) continue;
                    int np = (i2 * SS + j2) * TT + t2;
                    acc += w[dt*9 + di*3 + dj] * x[((size_t)(1 + np) * NB + n) * CC + c];
                }
            }
        }
        g_XBUF[((size_t)token * NB + n) * CC + c] = xb[c] + acc;
    }
}

// ---------------- LayerNorm -> fp16 output ---------------------------------
__global__ void ln_kernel(const float* __restrict__ src,
                          const float* __restrict__ srcCls,
                          __half* __restrict__ dst,
                          const float* __restrict__ g, const float* __restrict__ b,
                          int mode, int srcOff) {
    int row = blockIdx.x;
    const float* xr;
    if (mode == 0) {
        xr = src + (size_t)(row + srcOff) * CC;
    } else {
        int ls = row / SB, bb = row % SB;
        int t = bb / NB, n = bb % NB;
        if (ls == 0) xr = srcCls + (size_t)n * CC;
        else         xr = src + (size_t)(((ls - 1) * TT + t) * NB + n) * CC;
    }
    int tid = threadIdx.x;
    float s = 0.f, s2 = 0.f;
    float v[4];
    #pragma unroll
    for (int it = 0; it < 4; it++) {
        float val = xr[tid + it * 256];
        v[it] = val; s += val; s2 += val * val;
    }
    __shared__ float red[2][8];
    for (int m = 16; m; m >>= 1) {
        s  += __shfl_xor_sync(~0u, s, m);
        s2 += __shfl_xor_sync(~0u, s2, m);
    }
    if ((tid & 31) == 0) { red[0][tid >> 5] = s; red[1][tid >> 5] = s2; }
    __syncthreads();
    s = 0.f; s2 = 0.f;
    #pragma unroll
    for (int w = 0; w < 8; w++) { s += red[0][w]; s2 += red[1][w]; }
    float mean = s * (1.f / CC);
    float var  = s2 * (1.f / CC) - mean * mean;
    float inv  = rsqrtf(var + 1e-5f);
    __half* dr = dst + (size_t)row * CC;
    #pragma unroll
    for (int it = 0; it < 4; it++) {
        int c = tid + it * 256;
        dr[c] = __float2half_rn((v[it] - mean) * inv * g[c] + b[c]);
    }
}

// ---------------- fp16 tensor-core GEMM, cp.async 4-stage pipeline ---------
// C[M,N] = A[M,K] @ W[N,K]^T + bias (+epilogue)
// MODE 0: fp32 store | 1: QuickGELU -> fp16 store | 2: residual add fp32
// A, W are fp16 natural row-major. 128x128 tile, BK=32 halves, 256 thr,
// 8 warps (2m x 4n), warp tile 64x32, mma m16n8k16 f16 with fp32 accum.
// smem row stride 40 halves (80B): 16B-aligned, conflict-free frag gathers.

#define HSTR 40
#define STAGE_HALF (2 * 128 * HSTR)          // 10240 halves = 20480B
#define GSTAGES 4
#define GSMEM_BYTES (GSTAGES * STAGE_HALF * 2)  // 81920

template<int MODE>
__global__ void __launch_bounds__(256, 2)
tgemm_kernel(const __half* __restrict__ A, const __half* __restrict__ W,
             const float* __restrict__ bias, const float* __restrict__ res,
             void* __restrict__ outv, int M, int N, int K) {
    extern __shared__ __half smh[];
    const int tid  = threadIdx.x;
    const int bm   = blockIdx.y * 128, bn = blockIdx.x * 128;
    const int lane = tid & 31, wid = tid >> 5;
    const int wm   = (wid & 1) << 6;       // 0 or 64
    const int wn   = (wid >> 1) << 5;      // 0,32,64,96
    const int fr   = lane >> 2;            // 0..7
    const int fc   = lane & 3;             // 0..3

    // loader role: tid<128 loads A row tid, else W row tid-128
    const int  lrow  = tid & 127;
    const bool loadA = tid < 128;
    const bool valid = loadA ? ((bm + lrow) < M) : true;
    const int  vsz   = valid ? 16 : 0;
    int grow = loadA ? (bm + lrow) : (bn + lrow);
    if (loadA && !valid) grow = M - 1;
    const __half* gRow = (loadA ? A : W) + (size_t)grow * K;
    unsigned sbase = (unsigned)__cvta_generic_to_shared(smh);
    const unsigned dRowOff = (loadA ? 0 : 128 * HSTR * 2) + lrow * (HSTR * 2);

    float acc[16][4];
    #pragma unroll
    for (int i = 0; i < 16; i++)
        #pragma unroll
        for (int j = 0; j < 4; j++) acc[i][j] = 0.f;

    const int NS = K >> 5;   // 32 halves per slab

    #pragma unroll
    for (int s = 0; s < GSTAGES - 1; s++) {
        unsigned d = sbase + (unsigned)(s * STAGE_HALF * 2) + dRowOff;
        const __half* gp = gRow + s * 32;
        #pragma unroll
        for (int c = 0; c < 4; c++)
            asm volatile("cp.async.cg.shared.global [%0], [%1], 16, %2;\n"
                         :: "r"(d + c * 16), "l"(gp + c * 8), "r"(vsz));
        asm volatile("cp.async.commit_group;\n");
    }

    for (int s = 0; s < NS; s++) {
        asm volatile("cp.async.wait_group %0;\n" :: "n"(GSTAGES - 2));
        __syncthreads();

        if (s + GSTAGES - 1 < NS) {
            int st = (s + GSTAGES - 1) & (GSTAGES - 1);
            unsigned d = sbase + (unsigned)(st * STAGE_HALF * 2) + dRowOff;
            const __half* gp = gRow + (s + GSTAGES - 1) * 32;
            #pragma unroll
            for (int c = 0; c < 4; c++)
                asm volatile("cp.async.cg.shared.global [%0], [%1], 16, %2;\n"
                             :: "r"(d + c * 16), "l"(gp + c * 8), "r"(vsz));
        }
        asm volatile("cp.async.commit_group;\n");

        const __half* smA = smh + (s & (GSTAGES - 1)) * STAGE_HALF;
        const __half* smB = smA + 128 * HSTR;

        #pragma unroll
        for (int kk = 0; kk < 32; kk += 16) {
            unsigned af[4][4], bf[4][2];
            #pragma unroll
            for (int mt = 0; mt < 4; mt++) {
                const __half* p = smA + (wm + mt * 16 + fr) * HSTR + kk + fc * 2;
                af[mt][0] = *(const unsigned*)(p);
                af[mt][1] = *(const unsigned*)(p + 8 * HSTR);
                af[mt][2] = *(const unsigned*)(p + 8);
                af[mt][3] = *(const unsigned*)(p + 8 * HSTR + 8);
            }
            #pragma unroll
            for (int nt = 0; nt < 4; nt++) {
                const __half* p = smB + (wn + nt * 8 + fr) * HSTR + kk + fc * 2;
                bf[nt][0] = *(const unsigned*)(p);
                bf[nt][1] = *(const unsigned*)(p + 8);
            }
            #pragma unroll
            for (int mt = 0; mt < 4; mt++)
                #pragma unroll
                for (int nt = 0; nt < 4; nt++) {
                    float* c = acc[mt * 4 + nt];
                    asm volatile(
                        "mma.sync.aligned.m16n8k16.row.col.f32.f16.f16.f32 "
                        "{%0,%1,%2,%3}, {%4,%5,%6,%7}, {%8,%9}, {%0,%1,%2,%3};\n"
                        : "+f"(c[0]), "+f"(c[1]), "+f"(c[2]), "+f"(c[3])
                        : "r"(af[mt][0]), "r"(af[mt][1]), "r"(af[mt][2]), "r"(af[mt][3]),
                          "r"(bf[nt][0]), "r"(bf[nt][1]));
                }
        }
    }

    // epilogue
    float* outF  = (float*)outv;
    __half2* outH = (__half2*)outv;
    const int erow = lane >> 2;            // 0..7
    const int ecol = (lane & 3) * 2;       // 0,2,4,6
    #pragma unroll
    for (int mt = 0; mt < 4; mt++) {
        #pragma unroll
        for (int nt = 0; nt < 4; nt++) {
            const float* c = acc[mt * 4 + nt];
            int col = bn + wn + nt * 8 + ecol;
            float bv0 = bias[col], bv1 = bias[col + 1];
            #pragma unroll
            for (int half = 0; half < 2; half++) {
                int row = bm + wm + mt * 16 + erow + half * 8;
                if (row < M) {
                    size_t off = (size_t)row * N + col;
                    float v0 = c[half * 2 + 0] + bv0;
                    float v1 = c[half * 2 + 1] + bv1;
                    if (MODE == 1) {
                        v0 = v0 / (1.f + expf(-1.702f * v0));
                        v1 = v1 / (1.f + expf(-1.702f * v1));
                        outH[off >> 1] = __floats2half2_rn(v0, v1);
                    } else {
                        if (MODE == 2) {
                            v0 += res[off];
                            v1 += res[off + 1];
                        }
                        outF[off]     = v0;
                        outF[off + 1] = v1;
                    }
                }
            }
        }
    }
}

// ---------------- Temporal attention: batch (n,l), seq T=8 -----------------
__global__ void temporal_attn_kernel(const float* __restrict__ rpb_t) {
    int bid = blockIdx.x;
    int h = bid & 15;
    int nl = bid >> 4;
    int n = nl & 7;
    int l = nl >> 3;
    __shared__ float Q[TT][HD + 1], K[TT][HD + 1], V[TT][HD + 1], P[TT][TT];
    int d = threadIdx.x;
    #pragma unroll
    for (int t = 0; t < TT; t++) {
        size_t r = (size_t)((l * TT + t) * NB + n);
        const float* q = g_QKV + r * 3072 + h * HD + d;
        Q[t][d] = q[0] * 0.125f;
        K[t][d] = q[1024];
        V[t][d] = q[2048];
    }
    __syncthreads();
    int tq = d >> 3, tk = d & 7;
    float s = rpb_t[(tq - tk + TT - 1) * NH + h];
    #pragma unroll
    for (int k = 0; k < HD; k++) s += Q[tq][k] * K[tk][k];
    float m = s;
    for (int msk = 4; msk; msk >>= 1) m = fmaxf(m, __shfl_xor_sync(~0u, m, msk));
    float p = expf(s - m);
    float sum = p;
    for (int msk = 4; msk; msk >>= 1) sum += __shfl_xor_sync(~0u, sum, msk);
    P[tq][tk] = p / sum;
    __syncthreads();
    #pragma unroll
    for (int t = 0; t < TT; t++) {
        float o = 0.f;
        #pragma unroll
        for (int k = 0; k < TT; k++) o += P[t][k] * V[k][d];
        g_ATTh[((size_t)((l * TT + t) * NB + n)) * CC + h * HD + d] = __float2half_rn(o);
    }
}

// ---------------- Spatial attention: batch 64, heads 16, seq 197 -----------
#define SPAT_SMEM_FLOATS (2 * LS * 65 + 64 + LS + 8 + 256)
__global__ void spatial_attn_kernel(const float* __restrict__ rpb_s) {
    extern __shared__ float sm[];
    float* Ks    = sm;
    float* Vs    = Ks + LS * 65;
    float* Qrow  = Vs + LS * 65;
    float* S     = Qrow + 64;
    float* wred  = S + LS;
    float* Opart = wred + 8;
    int b = blockIdx.x >> 4;
    int h = blockIdx.x & 15;
    int tid = threadIdx.x;

    for (int idx = tid; idx < LS * HD; idx += 256) {
        int ls = idx >> 6, d2 = idx & 63;
        const float* q = g_QKV + ((size_t)(ls * SB + b)) * 3072 + h * HD + d2;
        Ks[ls * 65 + d2] = q[1024];
        Vs[ls * 65 + d2] = q[2048];
    }
    __syncthreads();

    for (int q = 0; q < LS; q++) {
        if (tid < HD)
            Qrow[tid] = g_QKV[((size_t)(q * SB + b)) * 3072 + h * HD + tid] * 0.125f;
        __syncthreads();
        float s = -1e30f;
        if (tid < LS) {
            s = 0.f;
            #pragma unroll 8
            for (int d2 = 0; d2 < HD; d2++) s += Qrow[d2] * Ks[tid * 65 + d2];
            if (q > 0 && tid > 0) {
                int lq = q - 1, lk = tid - 1;
                int idx = (lq / SS - lk / SS + SS - 1) * (2 * SS - 1)
                        + (lq % SS - lk % SS + SS - 1);
                s += rpb_s[idx * NH + h];
            }
        }
        float m = s;
        for (int msk = 16; msk; msk >>= 1) m = fmaxf(m, __shfl_xor_sync(~0u, m, msk));
        if ((tid & 31) == 0) wred[tid >> 5] = m;
        __syncthreads();
        float gm = wred[0];
        #pragma unroll
        for (int w = 1; w < 8; w++) gm = fmaxf(gm, wred[w]);
        float p = (tid < LS) ? expf(s - gm) : 0.f;
        if (tid < LS) S[tid] = p;
        float su = p;
        for (int msk = 16; msk; msk >>= 1) su += __shfl_xor_sync(~0u, su, msk);
        __syncthreads();
        if ((tid & 31) == 0) wred[tid >> 5] = su;
        __syncthreads();
        float gs = 0.f;
        #pragma unroll
        for (int w = 0; w < 8; w++) gs += wred[w];
        float inv = 1.f / gs;

        int d2 = tid & 63, chunk = tid >> 6;
        float o = 0.f;
        for (int k = chunk; k < LS; k += 4) o += S[k] * Vs[k * 65 + d2];
        Opart[chunk * 64 + d2] = o;
        __syncthreads();
        if (tid < HD) {
            float oo = (Opart[tid] + Opart[64 + tid] + Opart[128 + tid]
                      + Opart[192 + tid]) * inv;
            g_ATTh[((size_t)(q * SB + b)) * CC + h * HD + tid] = __float2half_rn(oo);
        }
        __syncthreads();
    }
}

// ---------------- Spatial residual: scatter-add + cls mean -----------------
__global__ void spatial_residual_kernel() {
    int row = blockIdx.x;
    int token = row >> 3, n = row & 7;
    int tid = threadIdx.x;
    if (token == 0) {
        for (int c = tid; c < CC; c += 256) {
            float a = 0.f;
            #pragma unroll
            for (int t = 0; t < TT; t++)
                a += g_PROJ[((size_t)(t * NB + n)) * CC + c];
            g_XBUF[(size_t)row * CC + c] += a * 0.125f;
        }
    } else {
        int p = token - 1;
        int l = p >> 3, t = p & 7;
        size_t src = ((size_t)((l + 1) * SB + t * NB + n)) * CC;
        for (int c = tid; c < CC; c += 256)
            g_XBUF[(size_t)row * CC + c] += g_PROJ[src + c];
    }
}

// ---------------------------------------------------------------------------
extern "C" void kernel_launch(void* const* d_in, const int* in_sizes, int n_in,
                              void* d_out, int out_size) {
    const float* x      = (const float*)d_in[0];
    const float* pos_w  = (const float*)d_in[1];
    const float* pos_b  = (const float*)d_in[2];
    const float* ln_t_g = (const float*)d_in[3];
    const float* ln_t_b = (const float*)d_in[4];
    const float* rpb_t  = (const float*)d_in[5];
    const float* wqkv_t = (const float*)d_in[6];
    const float* bqkv_t = (const float*)d_in[7];
    const float* wo_t   = (const float*)d_in[8];
    const float* bo_t   = (const float*)d_in[9];
    const float* ln1_g  = (const float*)d_in[10];
    const float* ln1_b  = (const float*)d_in[11];
    const float* rpb_s  = (const float*)d_in[12];
    const float* wqkv_s = (const float*)d_in[13];
    const float* bqkv_s = (const float*)d_in[14];
    const float* wo_s   = (const float*)d_in[15];
    const float* bo_s   = (const float*)d_in[16];
    const float* ln2_g  = (const float*)d_in[17];
    const float* ln2_b  = (const float*)d_in[18];
    const float* fc_w   = (const float*)d_in[19];
    const float* fc_b   = (const float*)d_in[20];
    const float* proj_w = (const float*)d_in[21];
    const float* proj_b = (const float*)d_in[22];
    float* out = (float*)d_out;

    float *pX, *pQKV, *pPROJ, *pXT;
    __half *pLNh, *pATTh, *pHh, *pWTh;
    cudaGetSymbolAddress((void**)&pX,    g_XBUF);
    cudaGetSymbolAddress((void**)&pLNh,  g_LNh);
    cudaGetSymbolAddress((void**)&pQKV,  g_QKV);
    cudaGetSymbolAddress((void**)&pATTh, g_ATTh);
    cudaGetSymbolAddress((void**)&pPROJ, g_PROJ);
    cudaGetSymbolAddress((void**)&pXT,   g_XT);
    cudaGetSymbolAddress((void**)&pHh,   g_Hh);
    cudaGetSymbolAddress((void**)&pWTh,  g_WTh);

    int spatSmem = SPAT_SMEM_FLOATS * 4;
    cudaFuncSetAttribute(spatial_attn_kernel,
                         cudaFuncAttributeMaxDynamicSharedMemorySize, spatSmem);
    cudaFuncSetAttribute(tgemm_kernel<0>,
                         cudaFuncAttributeMaxDynamicSharedMemorySize, GSMEM_BYTES);
    cudaFuncSetAttribute(tgemm_kernel<1>,
                         cudaFuncAttributeMaxDynamicSharedMemorySize, GSMEM_BYTES);
    cudaFuncSetAttribute(tgemm_kernel<2>,
                         cudaFuncAttributeMaxDynamicSharedMemorySize, GSMEM_BYTES);

    // fp16 weight copies
    __half* wqkvT = pWTh;                    // 3M
    __half* woT   = pWTh + 3145728;          // 1M
    __half* wqkvS = pWTh + 4194304;          // 3M
    __half* woS   = pWTh + 7340032;          // 1M
    __half* fcW   = pWTh + 8388608;          // 4M
    __half* projW = pWTh + 12582912;         // 4M
    wprep_kernel<<<3072, 256>>>(wqkv_t, wqkvT, 3145728/4);
    wprep_kernel<<<1024, 256>>>(wo_t,   woT,   1048576/4);
    wprep_kernel<<<3072, 256>>>(wqkv_s, wqkvS, 3145728/4);
    wprep_kernel<<<1024, 256>>>(wo_s,   woS,   1048576/4);
    wprep_kernel<<<4096, 256>>>(fc_w,   fcW,   4194304/4);
    wprep_kernel<<<4096, 256>>>(proj_w, projW, 4194304/4);

    // Stage 1: positional conv embedding -> g_XBUF (residual stream)
    pos_embed_kernel<<<dim3(NTOK, NB), 256>>>(x, pos_w, pos_b);

    // Stage 2: temporal attention on patch rows -> xt_full (fp32) in pXT
    ln_kernel<<<PROWS, 256>>>(pX, nullptr, pLNh, ln_t_g, ln_t_b, 0, NB);
    tgemm_kernel<0><<<dim3(24, 98), 256, GSMEM_BYTES>>>(
        pLNh, wqkvT, bqkv_t, nullptr, pQKV, PROWS, 3072, 1024);
    temporal_attn_kernel<<<LL * NB * NH, 64>>>(rpb_t);
    tgemm_kernel<2><<<dim3(8, 98), 256, GSMEM_BYTES>>>(
        pATTh, woT, bo_t, pX + (size_t)NB * CC, pXT, PROWS, 1024, 1024);

    // Stage 3: spatial attention (seq 197 incl. cls)
    ln_kernel<<<SROWS, 256>>>(pXT, pX, pLNh, ln1_g, ln1_b, 1, 0);
    tgemm_kernel<0><<<dim3(24, 99), 256, GSMEM_BYTES>>>(
        pLNh, wqkvS, bqkv_s, nullptr, pQKV, SROWS, 3072, 1024);
    spatial_attn_kernel<<<SB * NH, 256, spatSmem>>>(rpb_s);
    tgemm_kernel<0><<<dim3(8, 99), 256, GSMEM_BYTES>>>(
        pATTh, woS, bo_s, nullptr, pPROJ, SROWS, 1024, 1024);
    spatial_residual_kernel<<<ROWS, 256>>>();

    // Stage 4: MLP with QuickGELU (hidden in fp16)
    ln_kernel<<<ROWS, 256>>>(pX, nullptr, pLNh, ln2_g, ln2_b, 0, 0);
    tgemm_kernel<1><<<dim3(32, 99), 256, GSMEM_BYTES>>>(
        pLNh, fcW, fc_b, nullptr, pHh, ROWS, 4096, 1024);
    tgemm_kernel<2><<<dim3(8, 99), 256, GSMEM_BYTES>>>(
        pHh, projW, proj_b, pX, out, ROWS, 1024, 4096);
}

// round 11
// speedup vs baseline: 4.2016x; 1.5950x over previous
#include <cuda_runtime.h>
#include <cuda_fp16.h>
#include <math.h>
#include <stdint.h>

#define TT 8
#define SS 14
#define LL 196            // S*S
#define NB 8
#define CC 1024
#define NH 16
#define HD 64
#define NTOK (1 + LL*TT)  // 1569
#define ROWS (NTOK*NB)    // 12552
#define PROWS (LL*TT*NB)  // 12544 patch rows
#define LS (LL + 1)       // 197 spatial seq
#define SB (TT*NB)        // 64 spatial batch
#define SROWS (LS*SB)     // 12608
#define BH   1024         // SB*NH spatial batch*heads
#define SKP 200           // S row pad (floats)
#define PKP 224           // P/Vt key pad (halves, mult of 32)

// ---------------- scratch (device globals; no allocations) ----------------
__device__ __align__(256) float  g_XBUF[(size_t)ROWS * CC];      // residual stream
__device__ __align__(256) __half g_LNh [(size_t)SROWS * CC];     // LN out (fp16)
__device__ __align__(256) __half g_QKVh[(size_t)SROWS * 3 * CC]; // qkv fp16
__device__ __align__(256) __half g_ATTh[(size_t)SROWS * CC];     // attn out (fp16)
__device__ __align__(256) float  g_PROJ[(size_t)SROWS * CC];     // spatial proj out
__device__ __align__(256) float  g_XT  [(size_t)PROWS * CC];     // xt_full fp32
__device__ __align__(256) __half g_Hh  [(size_t)ROWS * 4 * CC];  // MLP hidden (fp16)
__device__ __align__(256) __half g_WTh [16777216];               // fp16 weights
__device__ __align__(256) float  g_S   [(size_t)BH * LS * SKP];  // spatial scores fp32
__device__ __align__(256) __half g_P   [(size_t)BH * LS * PKP];  // probs fp16 (padded)
__device__ __align__(256) __half g_Vt  [(size_t)BH * HD * PKP];  // V^T fp16 (padded)
__device__ float g_ZERO[256];                                    // zero bias

// ---------------- weight prep: fp32 -> fp16 --------------------------------
__global__ void wprep_kernel(const float* __restrict__ s, __half* __restrict__ d,
                             int n4) {
    int i = blockIdx.x * 256 + threadIdx.x;
    if (i < n4) {
        float4 v = ((const float4*)s)[i];
        ((__half2*)d)[i * 2]     = __floats2half2_rn(v.x, v.y);
        ((__half2*)d)[i * 2 + 1] = __floats2half2_rn(v.z, v.w);
    }
}

// ---------------- Stage 1: depthwise 3x3x3 conv positional embedding ------
__global__ void pos_embed_kernel(const float* __restrict__ x,
                                 const float* __restrict__ pw,
                                 const float* __restrict__ pb) {
    int token = blockIdx.x, n = blockIdx.y, tid = threadIdx.x;
    if (token == 0) {
        for (int c = tid; c < CC; c += 256)
            g_XBUF[(size_t)n * CC + c] = x[(size_t)n * CC + c];
        return;
    }
    int p = token - 1;
    int l = p / TT, t = p % TT;
    int i = l / SS, j = l % SS;
    const float* xb = x + ((size_t)token * NB + n) * CC;
    for (int c = tid; c < CC; c += 256) {
        float acc = pb[c];
        const float* w = pw + (size_t)c * 27;
        #pragma unroll
        for (int dt = 0; dt < 3; dt++) {
            int t2 = t + dt - 1;
            if ((unsigned)t2 >= TT) continue;
            #pragma unroll
            for (int di = 0; di < 3; di++) {
                int i2 = i + di - 1;
                if ((unsigned)i2 >= SS) continue;
                #pragma unroll
                for (int dj = 0; dj < 3; dj++) {
                    int j2 = j + dj - 1;
                    if ((unsigned)j2 >= SS) continue;
                    int np = (i2 * SS + j2) * TT + t2;
                    acc += w[dt*9 + di*3 + dj] * x[((size_t)(1 + np) * NB + n) * CC + c];
                }
            }
        }
        g_XBUF[((size_t)token * NB + n) * CC + c] = xb[c] + acc;
    }
}

// ---------------- LayerNorm -> fp16 output ---------------------------------
__global__ void ln_kernel(const float* __restrict__ src,
                          const float* __restrict__ srcCls,
                          __half* __restrict__ dst,
                          const float* __restrict__ g, const float* __restrict__ b,
                          int mode, int srcOff) {
    int row = blockIdx.x;
    const float* xr;
    if (mode == 0) {
        xr = src + (size_t)(row + srcOff) * CC;
    } else {
        int ls = row / SB, bb = row % SB;
        int t = bb / NB, n = bb % NB;
        if (ls == 0) xr = srcCls + (size_t)n * CC;
        else         xr = src + (size_t)(((ls - 1) * TT + t) * NB + n) * CC;
    }
    int tid = threadIdx.x;
    float s = 0.f, s2 = 0.f;
    float v[4];
    #pragma unroll
    for (int it = 0; it < 4; it++) {
        float val = xr[tid + it * 256];
        v[it] = val; s += val; s2 += val * val;
    }
    __shared__ float red[2][8];
    for (int m = 16; m; m >>= 1) {
        s  += __shfl_xor_sync(~0u, s, m);
        s2 += __shfl_xor_sync(~0u, s2, m);
    }
    if ((tid & 31) == 0) { red[0][tid >> 5] = s; red[1][tid >> 5] = s2; }
    __syncthreads();
    s = 0.f; s2 = 0.f;
    #pragma unroll
    for (int w = 0; w < 8; w++) { s += red[0][w]; s2 += red[1][w]; }
    float mean = s * (1.f / CC);
    float var  = s2 * (1.f / CC) - mean * mean;
    float inv  = rsqrtf(var + 1e-5f);
    __half* dr = dst + (size_t)row * CC;
    #pragma unroll
    for (int it = 0; it < 4; it++) {
        int c = tid + it * 256;
        dr[c] = __float2half_rn((v[it] - mean) * inv * g[c] + b[c]);
    }
}

// ---------------- fp16 tensor-core GEMM, cp.async 4-stage pipeline ---------
// C[M,N] = A[M,K] @ B[N,K]^T + bias (+epilogue). Strided rows, batched.
// MODE 0: fp32 store | 1: QuickGELU->fp16 | 2: residual add fp32 | 3: fp16 store
// BATCH 0: none | 1: qkv-layout A/B (scores), S-out | 2: P/Vt in, qkv-scatter out
#define HSTR 40
#define STAGE_HALF (2 * 128 * HSTR)
#define GSTAGES 4
#define GSMEM_BYTES (GSTAGES * STAGE_HALF * 2)  // 81920

template<int MODE, int BATCH>
__global__ void __launch_bounds__(256, 2)
tgemm_kernel(const __half* __restrict__ A, size_t strideA,
             const __half* __restrict__ B, size_t strideB,
             const float* __restrict__ bias, const float* __restrict__ res,
             void* __restrict__ outv, size_t outStride,
             int M, int N, int K, int colLim) {
    extern __shared__ __half smh[];
    const int tid  = threadIdx.x;
    const int bm   = blockIdx.y * 128, bn = blockIdx.x * 128;
    const int z    = blockIdx.z;
    const int lane = tid & 31, wid = tid >> 5;
    const int wm   = (wid & 1) << 6;
    const int wn   = (wid >> 1) << 5;
    const int fr   = lane >> 2;
    const int fc   = lane & 3;

    size_t aoff = 0, boff = 0, ooff = 0;
    if (BATCH == 1) {
        size_t e = (size_t)(z >> 4) * 3072 + (size_t)(z & 15) * 64;
        aoff = e; boff = e;
        ooff = (size_t)z * LS * SKP;
    } else if (BATCH == 2) {
        aoff = (size_t)z * LS * PKP;
        boff = (size_t)z * HD * PKP;
        ooff = (size_t)(z >> 4) * 1024 + (size_t)(z & 15) * 64;
    }

    const int  lrow  = tid & 127;
    const bool loadA = tid < 128;
    int  growi = loadA ? (bm + lrow) : (bn + lrow);
    const bool valid = loadA ? (growi < M) : (growi < N);
    const int  vsz   = valid ? 16 : 0;
    if (!valid) growi = 0;
    const __half* gRow = (loadA ? (A + aoff) : (B + boff))
                       + (size_t)growi * (loadA ? strideA : strideB);
    unsigned sbase = (unsigned)__cvta_generic_to_shared(smh);
    const unsigned dRowOff = (loadA ? 0 : 128 * HSTR * 2) + lrow * (HSTR * 2);

    float acc[16][4];
    #pragma unroll
    for (int i = 0; i < 16; i++)
        #pragma unroll
        for (int j = 0; j < 4; j++) acc[i][j] = 0.f;

    const int NS = K >> 5;

    #pragma unroll
    for (int s = 0; s < GSTAGES - 1; s++) {
        if (s < NS) {
            unsigned d = sbase + (unsigned)(s * STAGE_HALF * 2) + dRowOff;
            const __half* gp = gRow + s * 32;
            #pragma unroll
            for (int c = 0; c < 4; c++)
                asm volatile("cp.async.cg.shared.global [%0], [%1], 16, %2;\n"
                             :: "r"(d + c * 16), "l"(gp + c * 8), "r"(vsz));
        }
        asm volatile("cp.async.commit_group;\n");
    }

    for (int s = 0; s < NS; s++) {
        asm volatile("cp.async.wait_group %0;\n" :: "n"(GSTAGES - 2));
        __syncthreads();

        if (s + GSTAGES - 1 < NS) {
            int st = (s + GSTAGES - 1) & (GSTAGES - 1);
            unsigned d = sbase + (unsigned)(st * STAGE_HALF * 2) + dRowOff;
            const __half* gp = gRow + (s + GSTAGES - 1) * 32;
            #pragma unroll
            for (int c = 0; c < 4; c++)
                asm volatile("cp.async.cg.shared.global [%0], [%1], 16, %2;\n"
                             :: "r"(d + c * 16), "l"(gp + c * 8), "r"(vsz));
        }
        asm volatile("cp.async.commit_group;\n");

        const __half* smA = smh + (s & (GSTAGES - 1)) * STAGE_HALF;
        const __half* smB = smA + 128 * HSTR;

        #pragma unroll
        for (int kk = 0; kk < 32; kk += 16) {
            unsigned af[4][4], bf[4][2];
            #pragma unroll
            for (int mt = 0; mt < 4; mt++) {
                const __half* p = smA + (wm + mt * 16 + fr) * HSTR + kk + fc * 2;
                af[mt][0] = *(const unsigned*)(p);
                af[mt][1] = *(const unsigned*)(p + 8 * HSTR);
                af[mt][2] = *(const unsigned*)(p + 8);
                af[mt][3] = *(const unsigned*)(p + 8 * HSTR + 8);
            }
            #pragma unroll
            for (int nt = 0; nt < 4; nt++) {
                const __half* p = smB + (wn + nt * 8 + fr) * HSTR + kk + fc * 2;
                bf[nt][0] = *(const unsigned*)(p);
                bf[nt][1] = *(const unsigned*)(p + 8);
            }
            #pragma unroll
            for (int mt = 0; mt < 4; mt++)
                #pragma unroll
                for (int nt = 0; nt < 4; nt++) {
                    float* c = acc[mt * 4 + nt];
                    asm volatile(
                        "mma.sync.aligned.m16n8k16.row.col.f32.f16.f16.f32 "
                        "{%0,%1,%2,%3}, {%4,%5,%6,%7}, {%8,%9}, {%0,%1,%2,%3};\n"
                        : "+f"(c[0]), "+f"(c[1]), "+f"(c[2]), "+f"(c[3])
                        : "r"(af[mt][0]), "r"(af[mt][1]), "r"(af[mt][2]), "r"(af[mt][3]),
                          "r"(bf[nt][0]), "r"(bf[nt][1]));
                }
        }
    }

    float*   outF = (float*)outv;
    __half2* outH = (__half2*)outv;
    const int erow = lane >> 2;
    const int ecol = (lane & 3) * 2;
    #pragma unroll
    for (int mt = 0; mt < 4; mt++) {
        #pragma unroll
        for (int nt = 0; nt < 4; nt++) {
            const float* c = acc[mt * 4 + nt];
            int col = bn + wn + nt * 8 + ecol;
            if (col >= colLim) continue;
            float bv0 = bias[col], bv1 = bias[col + 1];
            #pragma unroll
            for (int half = 0; half < 2; half++) {
                int row = bm + wm + mt * 16 + erow + half * 8;
                if (row < M) {
                    size_t off = ooff + (size_t)row * outStride + col;
                    float v0 = c[half * 2 + 0] + bv0;
                    float v1 = c[half * 2 + 1] + bv1;
                    if (MODE == 1) {
                        v0 = v0 / (1.f + expf(-1.702f * v0));
                        v1 = v1 / (1.f + expf(-1.702f * v1));
                        outH[off >> 1] = __floats2half2_rn(v0, v1);
                    } else if (MODE == 3) {
                        outH[off >> 1] = __floats2half2_rn(v0, v1);
                    } else {
                        if (MODE == 2) {
                            v0 += res[off];
                            v1 += res[off + 1];
                        }
                        outF[off]     = v0;
                        outF[off + 1] = v1;
                    }
                }
            }
        }
    }
}

// ---------------- spatial softmax: scale + rel-pos bias + normalize --------
// warp per query row; P fp16 normalized, zero-padded to PKP keys.
__global__ void softmax_kernel(const float* __restrict__ rpb_s) {
    int wid = threadIdx.x >> 5, lane = threadIdx.x & 31;
    int q = blockIdx.x * 4 + wid;
    if (q >= LS) return;
    int b = blockIdx.y, h = blockIdx.z;
    size_t sbase = ((size_t)(b * 16 + h) * LS + q) * SKP;
    size_t pbase = ((size_t)(b * 16 + h) * LS + q) * PKP;
    int qi = 0, qj = 0;
    if (q > 0) { qi = (q - 1) / SS; qj = (q - 1) % SS; }
    float sv[7];
    float mx = -1e30f;
    #pragma unroll
    for (int it = 0; it < 7; it++) {
        int k = lane + it * 32;
        float s = -1e30f;
        if (k < LS) {
            s = g_S[sbase + k] * 0.125f;
            if (q > 0 && k > 0) {
                int ki = (k - 1) / SS, kj = (k - 1) % SS;
                int idx = (qi - ki + SS - 1) * (2 * SS - 1) + (qj - kj + SS - 1);
                s += rpb_s[idx * NH + h];
            }
        }
        sv[it] = s;
        mx = fmaxf(mx, s);
    }
    for (int m = 16; m; m >>= 1) mx = fmaxf(mx, __shfl_xor_sync(~0u, mx, m));
    float sum = 0.f;
    #pragma unroll
    for (int it = 0; it < 7; it++) {
        float p = (sv[it] > -1e29f) ? expf(sv[it] - mx) : 0.f;
        sv[it] = p; sum += p;
    }
    for (int m = 16; m; m >>= 1) sum += __shfl_xor_sync(~0u, sum, m);
    float inv = 1.f / sum;
    #pragma unroll
    for (int it = 0; it < 7; it++) {
        int k = lane + it * 32;
        if (k < LS) g_P[pbase + k] = __float2half_rn(sv[it] * inv);
    }
    if (lane < PKP - LS) g_P[pbase + LS + lane] = __ushort_as_half(0);
}

// ---------------- V transpose: Vt[bh][d][key] fp16, key-padded -------------
__global__ void vt_kernel() {
    __shared__ unsigned vsm[LS * 33];   // half2 rows of 33 words (66 halves)
    int z = blockIdx.x;                 // bh
    int b = z >> 4, h = z & 15;
    int tid = threadIdx.x;              // 256
    for (int idx = tid; idx < LS * 32; idx += 256) {
        int ls = idx >> 5, dp = idx & 31;
        vsm[ls * 33 + dp] = *(const unsigned*)
            (g_QKVh + ((size_t)(ls * SB + b)) * 3072 + 2048 + h * 64 + dp * 2);
    }
    __syncthreads();
    const __half* vh = (const __half*)vsm;
    __half2* dst = (__half2*)(g_Vt + (size_t)z * HD * PKP);
    for (int idx = tid; idx < HD * (PKP / 2); idx += 256) {
        int d = idx / (PKP / 2), kp = idx % (PKP / 2);
        __half h0 = (2 * kp     < LS) ? vh[(2 * kp)     * 66 + d] : __ushort_as_half(0);
        __half h1 = (2 * kp + 1 < LS) ? vh[(2 * kp + 1) * 66 + d] : __ushort_as_half(0);
        dst[(size_t)d * (PKP / 2) + kp] = __halves2half2(h0, h1);
    }
}

// ---------------- Temporal attention: batch (n,l), seq T=8 -----------------
__global__ void temporal_attn_kernel(const float* __restrict__ rpb_t) {
    int bid = blockIdx.x;
    int h = bid & 15;
    int nl = bid >> 4;
    int n = nl & 7;
    int l = nl >> 3;
    __shared__ float Q[TT][HD + 1], K[TT][HD + 1], V[TT][HD + 1], P[TT][TT];
    int d = threadIdx.x;
    #pragma unroll
    for (int t = 0; t < TT; t++) {
        size_t r = (size_t)((l * TT + t) * NB + n);
        const __half* q = g_QKVh + r * 3072 + h * HD + d;
        Q[t][d] = __half2float(q[0]) * 0.125f;
        K[t][d] = __half2float(q[1024]);
        V[t][d] = __half2float(q[2048]);
    }
    __syncthreads();
    int tq = d >> 3, tk = d & 7;
    float s = rpb_t[(tq - tk + TT - 1) * NH + h];
    #pragma unroll
    for (int k = 0; k < HD; k++) s += Q[tq][k] * K[tk][k];
    float m = s;
    for (int msk = 4; msk; msk >>= 1) m = fmaxf(m, __shfl_xor_sync(~0u, m, msk));
    float p = expf(s - m);
    float sum = p;
    for (int msk = 4; msk; msk >>= 1) sum += __shfl_xor_sync(~0u, sum, msk);
    P[tq][tk] = p / sum;
    __syncthreads();
    #pragma unroll
    for (int t = 0; t < TT; t++) {
        float o = 0.f;
        #pragma unroll
        for (int k = 0; k < TT; k++) o += P[t][k] * V[k][d];
        g_ATTh[((size_t)((l * TT + t) * NB + n)) * CC + h * HD + d] = __float2half_rn(o);
    }
}

// ---------------- Spatial residual: scatter-add + cls mean -----------------
__global__ void spatial_residual_kernel() {
    int row = blockIdx.x;
    int token = row >> 3, n = row & 7;
    int tid = threadIdx.x;
    if (token == 0) {
        for (int c = tid; c < CC; c += 256) {
            float a = 0.f;
            #pragma unroll
            for (int t = 0; t < TT; t++)
                a += g_PROJ[((size_t)(t * NB + n)) * CC + c];
            g_XBUF[(size_t)row * CC + c] += a * 0.125f;
        }
    } else {
        int p = token - 1;
        int l = p >> 3, t = p & 7;
        size_t src = ((size_t)((l + 1) * SB + t * NB + n)) * CC;
        for (int c = tid; c < CC; c += 256)
            g_XBUF[(size_t)row * CC + c] += g_PROJ[src + c];
    }
}

// ---------------------------------------------------------------------------
extern "C" void kernel_launch(void* const* d_in, const int* in_sizes, int n_in,
                              void* d_out, int out_size) {
    const float* x      = (const float*)d_in[0];
    const float* pos_w  = (const float*)d_in[1];
    const float* pos_b  = (const float*)d_in[2];
    const float* ln_t_g = (const float*)d_in[3];
    const float* ln_t_b = (const float*)d_in[4];
    const float* rpb_t  = (const float*)d_in[5];
    const float* wqkv_t = (const float*)d_in[6];
    const float* bqkv_t = (const float*)d_in[7];
    const float* wo_t   = (const float*)d_in[8];
    const float* bo_t   = (const float*)d_in[9];
    const float* ln1_g  = (const float*)d_in[10];
    const float* ln1_b  = (const float*)d_in[11];
    const float* rpb_s  = (const float*)d_in[12];
    const float* wqkv_s = (const float*)d_in[13];
    const float* bqkv_s = (const float*)d_in[14];
    const float* wo_s   = (const float*)d_in[15];
    const float* bo_s   = (const float*)d_in[16];
    const float* ln2_g  = (const float*)d_in[17];
    const float* ln2_b  = (const float*)d_in[18];
    const float* fc_w   = (const float*)d_in[19];
    const float* fc_b   = (const float*)d_in[20];
    const float* proj_w = (const float*)d_in[21];
    const float* proj_b = (const float*)d_in[22];
    float* out = (float*)d_out;

    float *pX, *pPROJ, *pXT, *pS, *pZERO;
    __half *pLNh, *pQKVh, *pATTh, *pHh, *pWTh, *pP, *pVt;
    cudaGetSymbolAddress((void**)&pX,    g_XBUF);
    cudaGetSymbolAddress((void**)&pLNh,  g_LNh);
    cudaGetSymbolAddress((void**)&pQKVh, g_QKVh);
    cudaGetSymbolAddress((void**)&pATTh, g_ATTh);
    cudaGetSymbolAddress((void**)&pPROJ, g_PROJ);
    cudaGetSymbolAddress((void**)&pXT,   g_XT);
    cudaGetSymbolAddress((void**)&pHh,   g_Hh);
    cudaGetSymbolAddress((void**)&pWTh,  g_WTh);
    cudaGetSymbolAddress((void**)&pS,    g_S);
    cudaGetSymbolAddress((void**)&pP,    g_P);
    cudaGetSymbolAddress((void**)&pVt,   g_Vt);
    cudaGetSymbolAddress((void**)&pZERO, g_ZERO);

    #define SET_SMEM(k) cudaFuncSetAttribute(k, \
        cudaFuncAttributeMaxDynamicSharedMemorySize, GSMEM_BYTES)
    SET_SMEM((tgemm_kernel<0,0>)); SET_SMEM((tgemm_kernel<1,0>));
    SET_SMEM((tgemm_kernel<2,0>)); SET_SMEM((tgemm_kernel<3,0>));
    SET_SMEM((tgemm_kernel<0,1>)); SET_SMEM((tgemm_kernel<3,2>));

    // fp16 weight copies
    __half* wqkvT = pWTh;
    __half* woT   = pWTh + 3145728;
    __half* wqkvS = pWTh + 4194304;
    __half* woS   = pWTh + 7340032;
    __half* fcW   = pWTh + 8388608;
    __half* projW = pWTh + 12582912;
    wprep_kernel<<<3072, 256>>>(wqkv_t, wqkvT, 3145728/4);
    wprep_kernel<<<1024, 256>>>(wo_t,   woT,   1048576/4);
    wprep_kernel<<<3072, 256>>>(wqkv_s, wqkvS, 3145728/4);
    wprep_kernel<<<1024, 256>>>(wo_s,   woS,   1048576/4);
    wprep_kernel<<<4096, 256>>>(fc_w,   fcW,   4194304/4);
    wprep_kernel<<<4096, 256>>>(proj_w, projW, 4194304/4);

    // Stage 1: positional conv embedding -> g_XBUF (residual stream)
    pos_embed_kernel<<<dim3(NTOK, NB), 256>>>(x, pos_w, pos_b);

    // Stage 2: temporal attention on patch rows -> xt_full (fp32) in pXT
    ln_kernel<<<PROWS, 256>>>(pX, nullptr, pLNh, ln_t_g, ln_t_b, 0, NB);
    tgemm_kernel<3,0><<<dim3(24, 98, 1), 256, GSMEM_BYTES>>>(
        pLNh, 1024, wqkvT, 1024, bqkv_t, nullptr, pQKVh, 3072,
        PROWS, 3072, 1024, 3072);
    temporal_attn_kernel<<<LL * NB * NH, 64>>>(rpb_t);
    tgemm_kernel<2,0><<<dim3(8, 98, 1), 256, GSMEM_BYTES>>>(
        pATTh, 1024, woT, 1024, bo_t, pX + (size_t)NB * CC, pXT, 1024,
        PROWS, 1024, 1024, 1024);

    // Stage 3: spatial attention (seq 197 incl. cls) via batched GEMMs
    ln_kernel<<<SROWS, 256>>>(pXT, pX, pLNh, ln1_g, ln1_b, 1, 0);
    tgemm_kernel<3,0><<<dim3(24, 99, 1), 256, GSMEM_BYTES>>>(
        pLNh, 1024, wqkvS, 1024, bqkv_s, nullptr, pQKVh, 3072,
        SROWS, 3072, 1024, 3072);
    // scores: S[bh][q][k] = Q @ K^T  (batched over 1024 bh)
    tgemm_kernel<0,1><<<dim3(2, 2, BH), 256, GSMEM_BYTES>>>(
        pQKVh, (size_t)SB * 3072, pQKVh + 1024, (size_t)SB * 3072,
        pZERO, nullptr, pS, SKP, LS, LS, 64, 198);
    softmax_kernel<<<dim3((LS + 3) / 4, SB, NH), 128>>>(rpb_s);
    vt_kernel<<<BH, 256>>>();
    // AV: O = P @ Vt, scattered into g_ATTh qkv-token layout
    tgemm_kernel<3,2><<<dim3(1, 2, BH), 256, GSMEM_BYTES>>>(
        pP, PKP, pVt, PKP, pZERO, nullptr, pATTh, (size_t)SB * 1024,
        LS, HD, PKP, HD);
    tgemm_kernel<0,0><<<dim3(8, 99, 1), 256, GSMEM_BYTES>>>(
        pATTh, 1024, woS, 1024, bo_s, nullptr, pPROJ, 1024,
        SROWS, 1024, 1024, 1024);
    spatial_residual_kernel<<<ROWS, 256>>>();

    // Stage 4: MLP with QuickGELU (hidden in fp16)
    ln_kernel<<<ROWS, 256>>>(pX, nullptr, pLNh, ln2_g, ln2_b, 0, 0);
    tgemm_kernel<1,0><<<dim3(32, 99, 1), 256, GSMEM_BYTES>>>(
        pLNh, 1024, fcW, 1024, fc_b, nullptr, pHh, 4096,
        ROWS, 4096, 1024, 4096);
    tgemm_kernel<2,0><<<dim3(8, 99, 1), 256, GSMEM_BYTES>>>(
        pHh, 4096, projW, 4096, proj_b, pX, out, 1024,
        ROWS, 1024, 4096, 1024);
}

// round 12
// speedup vs baseline: 4.5303x; 1.0782x over previous
#include <cuda_runtime.h>
#include <cuda_fp16.h>
#include <math.h>
#include <stdint.h>

#define TT 8
#define SS 14
#define LL 196            // S*S
#define NB 8
#define CC 1024
#define NH 16
#define HD 64
#define NTOK (1 + LL*TT)  // 1569
#define ROWS (NTOK*NB)    // 12552
#define PROWS (LL*TT*NB)  // 12544 patch rows
#define LS (LL + 1)       // 197 spatial seq
#define SB (TT*NB)        // 64 spatial batch
#define SROWS (LS*SB)     // 12608
#define BH   1024         // SB*NH spatial batch*heads
#define SKP 200           // S row pad (floats)
#define PKP 224           // P/Vt key pad (halves, mult of 32)

// ---------------- scratch (device globals; no allocations) ----------------
__device__ __align__(256) float  g_XBUF[(size_t)ROWS * CC];      // residual stream
__device__ __align__(256) __half g_LNh [(size_t)SROWS * CC];     // LN out (fp16)
__device__ __align__(256) __half g_QKVh[(size_t)SROWS * 3 * CC]; // qkv fp16
__device__ __align__(256) __half g_ATTh[(size_t)SROWS * CC];     // attn out (fp16)
__device__ __align__(256) float  g_PROJ[(size_t)SROWS * CC];     // spatial proj out
__device__ __align__(256) float  g_XT  [(size_t)PROWS * CC];     // xt_full fp32
__device__ __align__(256) __half g_Hh  [(size_t)ROWS * 4 * CC];  // MLP hidden (fp16)
__device__ __align__(256) __half g_WTh [16777216];               // fp16 weights
__device__ __align__(256) float  g_S   [(size_t)BH * LS * SKP];  // spatial scores fp32
__device__ __align__(256) __half g_P   [(size_t)BH * LS * PKP];  // probs fp16 (padded)
__device__ __align__(256) __half g_Vt  [(size_t)BH * HD * PKP];  // V^T fp16 (padded)
__device__ float g_ZERO[256];                                    // zero bias

// ---------------- merged weight prep: fp32 -> fp16 (all 6 tensors) --------
struct W6 { const float* p[6]; };
__global__ void wprep_all_kernel(W6 ws, __half* __restrict__ d) {
    // cumulative float4 offsets matching g_WTh layout
    const int cum0 = 0, cum1 = 786432, cum2 = 1048576, cum3 = 1835008,
              cum4 = 2097152, cum5 = 3145728, cum6 = 4194304;
    int i = blockIdx.x * 256 + threadIdx.x;
    if (i >= cum6) return;
    int s; int base;
    if      (i < cum1) { s = 0; base = cum0; }
    else if (i < cum2) { s = 1; base = cum1; }
    else if (i < cum3) { s = 2; base = cum2; }
    else if (i < cum4) { s = 3; base = cum3; }
    else if (i < cum5) { s = 4; base = cum4; }
    else               { s = 5; base = cum5; }
    float4 v = ((const float4*)ws.p[s])[i - base];
    ((__half2*)d)[i * 2]     = __floats2half2_rn(v.x, v.y);
    ((__half2*)d)[i * 2 + 1] = __floats2half2_rn(v.z, v.w);
}

// ---------------- Stage 1 fused: depthwise conv pos-embed + LayerNorm_t ----
// block = (l, n): all 8 frames of one spatial site; conv neighbors read once
// serve 3 temporal taps. Outputs -> g_XBUF (residual) and LN_t -> g_LNh.
__global__ void __launch_bounds__(256)
pos_ln_kernel(const float* __restrict__ x, const float* __restrict__ pw,
              const float* __restrict__ pb,
              const float* __restrict__ g, const float* __restrict__ b) {
    __shared__ float rows[TT][CC];            // 32KB staged outputs
    __shared__ float reds[8][TT], reds2[8][TT];
    __shared__ float stat[TT][2];
    int l = blockIdx.x, n = blockIdx.y, tid = threadIdx.x;
    int i = l / SS, j = l % SS;
    int wid = tid >> 5, lane = tid & 31;
    float s[TT], s2[TT];
    #pragma unroll
    for (int t = 0; t < TT; t++) { s[t] = 0.f; s2[t] = 0.f; }

    if (l == 0) {  // cls row copy (once per n)
        for (int c = tid; c < CC; c += 256)
            g_XBUF[(size_t)n * CC + c] = x[(size_t)n * CC + c];
    }

    for (int ci = 0; ci < 4; ci++) {
        int c = ci * 256 + tid;
        float w[27];
        #pragma unroll
        for (int k = 0; k < 27; k++) w[k] = pw[(size_t)c * 27 + k];
        float acc[TT], xown[TT];
        #pragma unroll
        for (int t = 0; t < TT; t++) acc[t] = pb[c];
        #pragma unroll
        for (int di = 0; di < 3; di++) {
            int i2 = i + di - 1;
            if ((unsigned)i2 >= SS) continue;
            #pragma unroll
            for (int dj = 0; dj < 3; dj++) {
                int j2 = j + dj - 1;
                if ((unsigned)j2 >= SS) continue;
                int kidx = di * 3 + dj;
                const float* base = x + ((size_t)(1 + (i2 * SS + j2) * TT) * NB + n) * CC + c;
                bool cen = (di == 1 && dj == 1);
                #pragma unroll
                for (int t2 = 0; t2 < TT; t2++) {
                    float val = base[(size_t)t2 * NB * CC];
                    if (cen) xown[t2] = val;
                    if (t2 + 1 < TT) acc[t2 + 1] += w[kidx]      * val;  // dt=0
                    acc[t2]                      += w[9  + kidx] * val;  // dt=1
                    if (t2 > 0)      acc[t2 - 1] += w[18 + kidx] * val;  // dt=2
                }
            }
        }
        #pragma unroll
        for (int t = 0; t < TT; t++) {
            float v = xown[t] + acc[t];
            g_XBUF[((size_t)((1 + l * TT + t) * NB) + n) * CC + c] = v;
            rows[t][c] = v;
            s[t] += v; s2[t] += v * v;
        }
    }
    #pragma unroll
    for (int t = 0; t < TT; t++)
        for (int m = 16; m; m >>= 1) {
            s[t]  += __shfl_xor_sync(~0u, s[t],  m);
            s2[t] += __shfl_xor_sync(~0u, s2[t], m);
        }
    if (lane == 0) {
        #pragma unroll
        for (int t = 0; t < TT; t++) { reds[wid][t] = s[t]; reds2[wid][t] = s2[t]; }
    }
    __syncthreads();
    if (lane < 8) {                       // warp wid reduces token wid
        float a = reds[lane][wid], a2 = reds2[lane][wid];
        #pragma unroll
        for (int m = 4; m; m >>= 1) {
            a  += __shfl_xor_sync(0xffu, a,  m);
            a2 += __shfl_xor_sync(0xffu, a2, m);
        }
        if (lane == 0) {
            float mean = a * (1.f / CC);
            float var  = a2 * (1.f / CC) - mean * mean;
            stat[wid][0] = mean;
            stat[wid][1] = rsqrtf(var + 1e-5f);
        }
    }
    __syncthreads();
    for (int ci = 0; ci < 4; ci++) {
        int c = ci * 256 + tid;
        float gc = g[c], bc = b[c];
        #pragma unroll
        for (int t = 0; t < TT; t++) {
            float v = rows[t][c];
            g_LNh[((size_t)((l * TT + t) * NB) + n) * CC + c] =
                __float2half_rn((v - stat[t][0]) * stat[t][1] * gc + bc);
        }
    }
}

// ---------------- LayerNorm (mode 1: spatial gather) -> fp16 ---------------
__global__ void ln_kernel(const float* __restrict__ src,
                          const float* __restrict__ srcCls,
                          __half* __restrict__ dst,
                          const float* __restrict__ g, const float* __restrict__ b,
                          int mode, int srcOff) {
    int row = blockIdx.x;
    const float* xr;
    if (mode == 0) {
        xr = src + (size_t)(row + srcOff) * CC;
    } else {
        int ls = row / SB, bb = row % SB;
        int t = bb / NB, n = bb % NB;
        if (ls == 0) xr = srcCls + (size_t)n * CC;
        else         xr = src + (size_t)(((ls - 1) * TT + t) * NB + n) * CC;
    }
    int tid = threadIdx.x;
    float s = 0.f, s2 = 0.f;
    float v[4];
    #pragma unroll
    for (int it = 0; it < 4; it++) {
        float val = xr[tid + it * 256];
        v[it] = val; s += val; s2 += val * val;
    }
    __shared__ float red[2][8];
    for (int m = 16; m; m >>= 1) {
        s  += __shfl_xor_sync(~0u, s, m);
        s2 += __shfl_xor_sync(~0u, s2, m);
    }
    if ((tid & 31) == 0) { red[0][tid >> 5] = s; red[1][tid >> 5] = s2; }
    __syncthreads();
    s = 0.f; s2 = 0.f;
    #pragma unroll
    for (int w = 0; w < 8; w++) { s += red[0][w]; s2 += red[1][w]; }
    float mean = s * (1.f / CC);
    float var  = s2 * (1.f / CC) - mean * mean;
    float inv  = rsqrtf(var + 1e-5f);
    __half* dr = dst + (size_t)row * CC;
    #pragma unroll
    for (int it = 0; it < 4; it++) {
        int c = tid + it * 256;
        dr[c] = __float2half_rn((v[it] - mean) * inv * g[c] + b[c]);
    }
}

// ---------------- fused spatial residual + LayerNorm2 ----------------------
// XBUF += spatial proj (scatter + cls mean); then LN -> g_LNh. One pass.
__global__ void resid_ln_kernel(const float* __restrict__ g,
                                const float* __restrict__ b) {
    int row = blockIdx.x, tid = threadIdx.x;
    int token = row >> 3, n = row & 7;
    float v[4];
    float s = 0.f, s2 = 0.f;
    #pragma unroll
    for (int it = 0; it < 4; it++) {
        int c = tid + it * 256;
        float base = g_XBUF[(size_t)row * CC + c];
        float add;
        if (token == 0) {
            float a = 0.f;
            #pragma unroll
            for (int t = 0; t < TT; t++)
                a += g_PROJ[((size_t)(t * NB + n)) * CC + c];
            add = a * 0.125f;
        } else {
            int p = token - 1;
            int l = p >> 3, t = p & 7;
            add = g_PROJ[((size_t)((l + 1) * SB + t * NB + n)) * CC + c];
        }
        float vv = base + add;
        g_XBUF[(size_t)row * CC + c] = vv;
        v[it] = vv; s += vv; s2 += vv * vv;
    }
    __shared__ float red[2][8];
    for (int m = 16; m; m >>= 1) {
        s  += __shfl_xor_sync(~0u, s, m);
        s2 += __shfl_xor_sync(~0u, s2, m);
    }
    if ((tid & 31) == 0) { red[0][tid >> 5] = s; red[1][tid >> 5] = s2; }
    __syncthreads();
    s = 0.f; s2 = 0.f;
    #pragma unroll
    for (int w = 0; w < 8; w++) { s += red[0][w]; s2 += red[1][w]; }
    float mean = s * (1.f / CC);
    float var  = s2 * (1.f / CC) - mean * mean;
    float inv  = rsqrtf(var + 1e-5f);
    __half* dr = g_LNh + (size_t)row * CC;
    #pragma unroll
    for (int it = 0; it < 4; it++) {
        int c = tid + it * 256;
        dr[c] = __float2half_rn((v[it] - mean) * inv * g[c] + b[c]);
    }
}

// ---------------- fp16 tensor-core GEMM, cp.async 4-stage pipeline ---------
// C[M,N] = A[M,K] @ B[N,K]^T + bias (+epilogue). Strided rows, batched.
// MODE 0: fp32 store | 1: QuickGELU->fp16 | 2: residual add fp32 | 3: fp16 store
// BATCH 0: none | 1: qkv-layout A/B (scores), S-out | 2: P/Vt in, qkv-scatter out
#define HSTR 40
#define STAGE_HALF (2 * 128 * HSTR)
#define GSTAGES 4
#define GSMEM_BYTES (GSTAGES * STAGE_HALF * 2)  // 81920

template<int MODE, int BATCH>
__global__ void __launch_bounds__(256, 2)
tgemm_kernel(const __half* __restrict__ A, size_t strideA,
             const __half* __restrict__ B, size_t strideB,
             const float* __restrict__ bias, const float* __restrict__ res,
             void* __restrict__ outv, size_t outStride,
             int M, int N, int K, int colLim) {
    extern __shared__ __half smh[];
    const int tid  = threadIdx.x;
    const int bm   = blockIdx.y * 128, bn = blockIdx.x * 128;
    const int z    = blockIdx.z;
    const int lane = tid & 31, wid = tid >> 5;
    const int wm   = (wid & 1) << 6;
    const int wn   = (wid >> 1) << 5;
    const int fr   = lane >> 2;
    const int fc   = lane & 3;

    size_t aoff = 0, boff = 0, ooff = 0;
    if (BATCH == 1) {
        size_t e = (size_t)(z >> 4) * 3072 + (size_t)(z & 15) * 64;
        aoff = e; boff = e;
        ooff = (size_t)z * LS * SKP;
    } else if (BATCH == 2) {
        aoff = (size_t)z * LS * PKP;
        boff = (size_t)z * HD * PKP;
        ooff = (size_t)(z >> 4) * 1024 + (size_t)(z & 15) * 64;
    }

    const int  lrow  = tid & 127;
    const bool loadA = tid < 128;
    int  growi = loadA ? (bm + lrow) : (bn + lrow);
    const bool valid = loadA ? (growi < M) : (growi < N);
    const int  vsz   = valid ? 16 : 0;
    if (!valid) growi = 0;
    const __half* gRow = (loadA ? (A + aoff) : (B + boff))
                       + (size_t)growi * (loadA ? strideA : strideB);
    unsigned sbase = (unsigned)__cvta_generic_to_shared(smh);
    const unsigned dRowOff = (loadA ? 0 : 128 * HSTR * 2) + lrow * (HSTR * 2);

    float acc[16][4];
    #pragma unroll
    for (int i = 0; i < 16; i++)
        #pragma unroll
        for (int j = 0; j < 4; j++) acc[i][j] = 0.f;

    const int NS = K >> 5;

    #pragma unroll
    for (int s = 0; s < GSTAGES - 1; s++) {
        if (s < NS) {
            unsigned d = sbase + (unsigned)(s * STAGE_HALF * 2) + dRowOff;
            const __half* gp = gRow + s * 32;
            #pragma unroll
            for (int c = 0; c < 4; c++)
                asm volatile("cp.async.cg.shared.global [%0], [%1], 16, %2;\n"
                             :: "r"(d + c * 16), "l"(gp + c * 8), "r"(vsz));
        }
        asm volatile("cp.async.commit_group;\n");
    }

    for (int s = 0; s < NS; s++) {
        asm volatile("cp.async.wait_group %0;\n" :: "n"(GSTAGES - 2));
        __syncthreads();

        if (s + GSTAGES - 1 < NS) {
            int st = (s + GSTAGES - 1) & (GSTAGES - 1);
            unsigned d = sbase + (unsigned)(st * STAGE_HALF * 2) + dRowOff;
            const __half* gp = gRow + (s + GSTAGES - 1) * 32;
            #pragma unroll
            for (int c = 0; c < 4; c++)
                asm volatile("cp.async.cg.shared.global [%0], [%1], 16, %2;\n"
                             :: "r"(d + c * 16), "l"(gp + c * 8), "r"(vsz));
        }
        asm volatile("cp.async.commit_group;\n");

        const __half* smA = smh + (s & (GSTAGES - 1)) * STAGE_HALF;
        const __half* smB = smA + 128 * HSTR;

        #pragma unroll
        for (int kk = 0; kk < 32; kk += 16) {
            unsigned af[4][4], bf[4][2];
            #pragma unroll
            for (int mt = 0; mt < 4; mt++) {
                const __half* p = smA + (wm + mt * 16 + fr) * HSTR + kk + fc * 2;
                af[mt][0] = *(const unsigned*)(p);
                af[mt][1] = *(const unsigned*)(p + 8 * HSTR);
                af[mt][2] = *(const unsigned*)(p + 8);
                af[mt][3] = *(const unsigned*)(p + 8 * HSTR + 8);
            }
            #pragma unroll
            for (int nt = 0; nt < 4; nt++) {
                const __half* p = smB + (wn + nt * 8 + fr) * HSTR + kk + fc * 2;
                bf[nt][0] = *(const unsigned*)(p);
                bf[nt][1] = *(const unsigned*)(p + 8);
            }
            #pragma unroll
            for (int mt = 0; mt < 4; mt++)
                #pragma unroll
                for (int nt = 0; nt < 4; nt++) {
                    float* c = acc[mt * 4 + nt];
                    asm volatile(
                        "mma.sync.aligned.m16n8k16.row.col.f32.f16.f16.f32 "
                        "{%0,%1,%2,%3}, {%4,%5,%6,%7}, {%8,%9}, {%0,%1,%2,%3};\n"
                        : "+f"(c[0]), "+f"(c[1]), "+f"(c[2]), "+f"(c[3])
                        : "r"(af[mt][0]), "r"(af[mt][1]), "r"(af[mt][2]), "r"(af[mt][3]),
                          "r"(bf[nt][0]), "r"(bf[nt][1]));
                }
        }
    }

    float*   outF = (float*)outv;
    __half2* outH = (__half2*)outv;
    const int erow = lane >> 2;
    const int ecol = (lane & 3) * 2;
    #pragma unroll
    for (int mt = 0; mt < 4; mt++) {
        #pragma unroll
        for (int nt = 0; nt < 4; nt++) {
            const float* c = acc[mt * 4 + nt];
            int col = bn + wn + nt * 8 + ecol;
            if (col >= colLim) continue;
            float bv0 = bias[col], bv1 = bias[col + 1];
            #pragma unroll
            for (int half = 0; half < 2; half++) {
                int row = bm + wm + mt * 16 + erow + half * 8;
                if (row < M) {
                    size_t off = ooff + (size_t)row * outStride + col;
                    float v0 = c[half * 2 + 0] + bv0;
                    float v1 = c[half * 2 + 1] + bv1;
                    if (MODE == 1) {
                        v0 = v0 / (1.f + expf(-1.702f * v0));
                        v1 = v1 / (1.f + expf(-1.702f * v1));
                        outH[off >> 1] = __floats2half2_rn(v0, v1);
                    } else if (MODE == 3) {
                        outH[off >> 1] = __floats2half2_rn(v0, v1);
                    } else {
                        if (MODE == 2) {
                            v0 += res[off];
                            v1 += res[off + 1];
                        }
                        outF[off]     = v0;
                        outF[off + 1] = v1;
                    }
                }
            }
        }
    }
}

// ---------------- spatial softmax: scale + rel-pos bias + normalize --------
__global__ void softmax_kernel(const float* __restrict__ rpb_s) {
    int wid = threadIdx.x >> 5, lane = threadIdx.x & 31;
    int q = blockIdx.x * 4 + wid;
    if (q >= LS) return;
    int b = blockIdx.y, h = blockIdx.z;
    size_t sbase = ((size_t)(b * 16 + h) * LS + q) * SKP;
    size_t pbase = ((size_t)(b * 16 + h) * LS + q) * PKP;
    int qi = 0, qj = 0;
    if (q > 0) { qi = (q - 1) / SS; qj = (q - 1) % SS; }
    float sv[7];
    float mx = -1e30f;
    #pragma unroll
    for (int it = 0; it < 7; it++) {
        int k = lane + it * 32;
        float s = -1e30f;
        if (k < LS) {
            s = g_S[sbase + k] * 0.125f;
            if (q > 0 && k > 0) {
                int ki = (k - 1) / SS, kj = (k - 1) % SS;
                int idx = (qi - ki + SS - 1) * (2 * SS - 1) + (qj - kj + SS - 1);
                s += rpb_s[idx * NH + h];
            }
        }
        sv[it] = s;
        mx = fmaxf(mx, s);
    }
    for (int m = 16; m; m >>= 1) mx = fmaxf(mx, __shfl_xor_sync(~0u, mx, m));
    float sum = 0.f;
    #pragma unroll
    for (int it = 0; it < 7; it++) {
        float p = (sv[it] > -1e29f) ? expf(sv[it] - mx) : 0.f;
        sv[it] = p; sum += p;
    }
    for (int m = 16; m; m >>= 1) sum += __shfl_xor_sync(~0u, sum, m);
    float inv = 1.f / sum;
    #pragma unroll
    for (int it = 0; it < 7; it++) {
        int k = lane + it * 32;
        if (k < LS) g_P[pbase + k] = __float2half_rn(sv[it] * inv);
    }
    if (lane < PKP - LS) g_P[pbase + LS + lane] = __ushort_as_half(0);
}

// ---------------- V transpose: Vt[bh][d][key] fp16, key-padded -------------
__global__ void vt_kernel() {
    __shared__ unsigned vsm[LS * 33];   // half2 rows of 33 words (66 halves)
    int z = blockIdx.x;                 // bh
    int b = z >> 4, h = z & 15;
    int tid = threadIdx.x;              // 256
    for (int idx = tid; idx < LS * 32; idx += 256) {
        int ls = idx >> 5, dp = idx & 31;
        vsm[ls * 33 + dp] = *(const unsigned*)
            (g_QKVh + ((size_t)(ls * SB + b)) * 3072 + 2048 + h * 64 + dp * 2);
    }
    __syncthreads();
    const __half* vh = (const __half*)vsm;
    __half2* dst = (__half2*)(g_Vt + (size_t)z * HD * PKP);
    for (int idx = tid; idx < HD * (PKP / 2); idx += 256) {
        int d = idx / (PKP / 2), kp = idx % (PKP / 2);
        __half h0 = (2 * kp     < LS) ? vh[(2 * kp)     * 66 + d] : __ushort_as_half(0);
        __half h1 = (2 * kp + 1 < LS) ? vh[(2 * kp + 1) * 66 + d] : __ushort_as_half(0);
        dst[(size_t)d * (PKP / 2) + kp] = __halves2half2(h0, h1);
    }
}

// ---------------- Temporal attention: batch (n,l), seq T=8 -----------------
__global__ void temporal_attn_kernel(const float* __restrict__ rpb_t) {
    int bid = blockIdx.x;
    int h = bid & 15;
    int nl = bid >> 4;
    int n = nl & 7;
    int l = nl >> 3;
    __shared__ float Q[TT][HD + 1], K[TT][HD + 1], V[TT][HD + 1], P[TT][TT];
    int d = threadIdx.x;
    #pragma unroll
    for (int t = 0; t < TT; t++) {
        size_t r = (size_t)((l * TT + t) * NB + n);
        const __half* q = g_QKVh + r * 3072 + h * HD + d;
        Q[t][d] = __half2float(q[0]) * 0.125f;
        K[t][d] = __half2float(q[1024]);
        V[t][d] = __half2float(q[2048]);
    }
    __syncthreads();
    int tq = d >> 3, tk = d & 7;
    float s = rpb_t[(tq - tk + TT - 1) * NH + h];
    #pragma unroll
    for (int k = 0; k < HD; k++) s += Q[tq][k] * K[tk][k];
    float m = s;
    for (int msk = 4; msk; msk >>= 1) m = fmaxf(m, __shfl_xor_sync(~0u, m, msk));
    float p = expf(s - m);
    float sum = p;
    for (int msk = 4; msk; msk >>= 1) sum += __shfl_xor_sync(~0u, sum, msk);
    P[tq][tk] = p / sum;
    __syncthreads();
    #pragma unroll
    for (int t = 0; t < TT; t++) {
        float o = 0.f;
        #pragma unroll
        for (int k = 0; k < TT; k++) o += P[t][k] * V[k][d];
        g_ATTh[((size_t)((l * TT + t) * NB + n)) * CC + h * HD + d] = __float2half_rn(o);
    }
}

// ---------------------------------------------------------------------------
extern "C" void kernel_launch(void* const* d_in, const int* in_sizes, int n_in,
                              void* d_out, int out_size) {
    const float* x      = (const float*)d_in[0];
    const float* pos_w  = (const float*)d_in[1];
    const float* pos_b  = (const float*)d_in[2];
    const float* ln_t_g = (const float*)d_in[3];
    const float* ln_t_b = (const float*)d_in[4];
    const float* rpb_t  = (const float*)d_in[5];
    const float* wqkv_t = (const float*)d_in[6];
    const float* bqkv_t = (const float*)d_in[7];
    const float* wo_t   = (const float*)d_in[8];
    const float* bo_t   = (const float*)d_in[9];
    const float* ln1_g  = (const float*)d_in[10];
    const float* ln1_b  = (const float*)d_in[11];
    const float* rpb_s  = (const float*)d_in[12];
    const float* wqkv_s = (const float*)d_in[13];
    const float* bqkv_s = (const float*)d_in[14];
    const float* wo_s   = (const float*)d_in[15];
    const float* bo_s   = (const float*)d_in[16];
    const float* ln2_g  = (const float*)d_in[17];
    const float* ln2_b  = (const float*)d_in[18];
    const float* fc_w   = (const float*)d_in[19];
    const float* fc_b   = (const float*)d_in[20];
    const float* proj_w = (const float*)d_in[21];
    const float* proj_b = (const float*)d_in[22];
    float* out = (float*)d_out;

    float *pX, *pPROJ, *pXT, *pS, *pZERO;
    __half *pLNh, *pQKVh, *pATTh, *pHh, *pWTh, *pP, *pVt;
    cudaGetSymbolAddress((void**)&pX,    g_XBUF);
    cudaGetSymbolAddress((void**)&pLNh,  g_LNh);
    cudaGetSymbolAddress((void**)&pQKVh, g_QKVh);
    cudaGetSymbolAddress((void**)&pATTh, g_ATTh);
    cudaGetSymbolAddress((void**)&pPROJ, g_PROJ);
    cudaGetSymbolAddress((void**)&pXT,   g_XT);
    cudaGetSymbolAddress((void**)&pHh,   g_Hh);
    cudaGetSymbolAddress((void**)&pWTh,  g_WTh);
    cudaGetSymbolAddress((void**)&pS,    g_S);
    cudaGetSymbolAddress((void**)&pP,    g_P);
    cudaGetSymbolAddress((void**)&pVt,   g_Vt);
    cudaGetSymbolAddress((void**)&pZERO, g_ZERO);

    #define SET_SMEM(k) cudaFuncSetAttribute(k, \
        cudaFuncAttributeMaxDynamicSharedMemorySize, GSMEM_BYTES)
    SET_SMEM((tgemm_kernel<0,0>)); SET_SMEM((tgemm_kernel<1,0>));
    SET_SMEM((tgemm_kernel<2,0>)); SET_SMEM((tgemm_kernel<3,0>));
    SET_SMEM((tgemm_kernel<0,1>)); SET_SMEM((tgemm_kernel<3,2>));

    // fp16 weight copies (contiguous arena; one merged prep launch)
    __half* wqkvT = pWTh;
    __half* woT   = pWTh + 3145728;
    __half* wqkvS = pWTh + 4194304;
    __half* woS   = pWTh + 7340032;
    __half* fcW   = pWTh + 8388608;
    __half* projW = pWTh + 12582912;
    W6 ws;
    ws.p[0] = wqkv_t; ws.p[1] = wo_t; ws.p[2] = wqkv_s;
    ws.p[3] = wo_s;   ws.p[4] = fc_w; ws.p[5] = proj_w;
    wprep_all_kernel<<<16384, 256>>>(ws, pWTh);

    // Stage 1+LN_t fused: conv pos embed -> XBUF, LN_t -> LNh
    pos_ln_kernel<<<dim3(LL, NB), 256>>>(x, pos_w, pos_b, ln_t_g, ln_t_b);

    // Stage 2: temporal attention on patch rows -> xt_full (fp32) in pXT
    tgemm_kernel<3,0><<<dim3(24, 98, 1), 256, GSMEM_BYTES>>>(
        pLNh, 1024, wqkvT, 1024, bqkv_t, nullptr, pQKVh, 3072,
        PROWS, 3072, 1024, 3072);
    temporal_attn_kernel<<<LL * NB * NH, 64>>>(rpb_t);
    tgemm_kernel<2,0><<<dim3(8, 98, 1), 256, GSMEM_BYTES>>>(
        pATTh, 1024, woT, 1024, bo_t, pX + (size_t)NB * CC, pXT, 1024,
        PROWS, 1024, 1024, 1024);

    // Stage 3: spatial attention (seq 197 incl. cls) via batched GEMMs
    ln_kernel<<<SROWS, 256>>>(pXT, pX, pLNh, ln1_g, ln1_b, 1, 0);
    tgemm_kernel<3,0><<<dim3(24, 99, 1), 256, GSMEM_BYTES>>>(
        pLNh, 1024, wqkvS, 1024, bqkv_s, nullptr, pQKVh, 3072,
        SROWS, 3072, 1024, 3072);
    tgemm_kernel<0,1><<<dim3(2, 2, BH), 256, GSMEM_BYTES>>>(
        pQKVh, (size_t)SB * 3072, pQKVh + 1024, (size_t)SB * 3072,
        pZERO, nullptr, pS, SKP, LS, LS, 64, 198);
    softmax_kernel<<<dim3((LS + 3) / 4, SB, NH), 128>>>(rpb_s);
    vt_kernel<<<BH, 256>>>();
    tgemm_kernel<3,2><<<dim3(1, 2, BH), 256, GSMEM_BYTES>>>(
        pP, PKP, pVt, PKP, pZERO, nullptr, pATTh, (size_t)SB * 1024,
        LS, HD, PKP, HD);
    tgemm_kernel<0,0><<<dim3(8, 99, 1), 256, GSMEM_BYTES>>>(
        pATTh, 1024, woS, 1024, bo_s, nullptr, pPROJ, 1024,
        SROWS, 1024, 1024, 1024);

    // fused: spatial residual (+cls mean) into XBUF, then LN2 -> LNh
    resid_ln_kernel<<<ROWS, 256>>>(ln2_g, ln2_b);

    // Stage 4: MLP with QuickGELU (hidden in fp16)
    tgemm_kernel<1,0><<<dim3(32, 99, 1), 256, GSMEM_BYTES>>>(
        pLNh, 1024, fcW, 1024, fc_b, nullptr, pHh, 4096,
        ROWS, 4096, 1024, 4096);
    tgemm_kernel<2,0><<<dim3(8, 99, 1), 256, GSMEM_BYTES>>>(
        pHh, 4096, projW, 4096, proj_b, pX, out, 1024,
        ROWS, 1024, 4096, 1024);
}

// round 13
// speedup vs baseline: 5.0678x; 1.1186x over previous
#include <cuda_runtime.h>
#include <cuda_fp16.h>
#include <math.h>
#include <stdint.h>

#define TT 8
#define SS 14
#define LL 196            // S*S
#define NB 8
#define CC 1024
#define NH 16
#define HD 64
#define NTOK (1 + LL*TT)  // 1569
#define ROWS (NTOK*NB)    // 12552
#define PROWS (LL*TT*NB)  // 12544 patch rows
#define LS (LL + 1)       // 197 spatial seq
#define SB (TT*NB)        // 64 spatial batch
#define SROWS (LS*SB)     // 12608
#define BH   1024         // SB*NH spatial batch*heads
#define SKP 200           // S row pad (floats)
#define PKP 224           // P/Vt key pad (halves, mult of 32)

// ---------------- scratch (device globals; no allocations) ----------------
__device__ __align__(256) float  g_XBUF[(size_t)ROWS * CC];      // residual stream
__device__ __align__(256) __half g_LNh [(size_t)SROWS * CC];     // LN out (fp16)
__device__ __align__(256) __half g_QKVh[(size_t)SROWS * 3 * CC]; // qkv fp16
__device__ __align__(256) __half g_ATTh[(size_t)SROWS * CC];     // attn out (fp16)
__device__ __align__(256) float  g_PROJ[(size_t)SROWS * CC];     // spatial proj out
__device__ __align__(256) float  g_XT  [(size_t)PROWS * CC];     // xt_full fp32
__device__ __align__(256) __half g_Hh  [(size_t)ROWS * 4 * CC];  // MLP hidden (fp16)
__device__ __align__(256) __half g_WTh [16777216];               // fp16 weights
__device__ __align__(256) float  g_S   [(size_t)BH * LS * SKP];  // spatial scores fp32
__device__ __align__(256) __half g_P   [(size_t)BH * LS * PKP];  // probs fp16 (padded)
__device__ __align__(256) __half g_Vt  [(size_t)BH * HD * PKP];  // V^T fp16 (padded)
__device__ float g_ZERO[256];                                    // zero bias

// ---------------- merged weight prep: fp32 -> fp16 (all 6 tensors) --------
struct W6 { const float* p[6]; };
__global__ void wprep_all_kernel(W6 ws, __half* __restrict__ d) {
    const int cum1 = 786432, cum2 = 1048576, cum3 = 1835008,
              cum4 = 2097152, cum5 = 3145728, cum6 = 4194304;
    int i = blockIdx.x * 256 + threadIdx.x;
    if (i >= cum6) return;
    int s; int base;
    if      (i < cum1) { s = 0; base = 0; }
    else if (i < cum2) { s = 1; base = cum1; }
    else if (i < cum3) { s = 2; base = cum2; }
    else if (i < cum4) { s = 3; base = cum3; }
    else if (i < cum5) { s = 4; base = cum4; }
    else               { s = 5; base = cum5; }
    float4 v = ((const float4*)ws.p[s])[i - base];
    ((__half2*)d)[i * 2]     = __floats2half2_rn(v.x, v.y);
    ((__half2*)d)[i * 2 + 1] = __floats2half2_rn(v.z, v.w);
}

// ---------------- Stage 1 fused: depthwise conv pos-embed + LayerNorm_t ----
__global__ void __launch_bounds__(256)
pos_ln_kernel(const float* __restrict__ x, const float* __restrict__ pw,
              const float* __restrict__ pb,
              const float* __restrict__ g, const float* __restrict__ b) {
    __shared__ float rows[TT][CC];
    __shared__ float reds[8][TT], reds2[8][TT];
    __shared__ float stat[TT][2];
    int l = blockIdx.x, n = blockIdx.y, tid = threadIdx.x;
    int i = l / SS, j = l % SS;
    int wid = tid >> 5, lane = tid & 31;
    float s[TT], s2[TT];
    #pragma unroll
    for (int t = 0; t < TT; t++) { s[t] = 0.f; s2[t] = 0.f; }

    if (l == 0) {
        for (int c = tid; c < CC; c += 256)
            g_XBUF[(size_t)n * CC + c] = x[(size_t)n * CC + c];
    }

    for (int ci = 0; ci < 4; ci++) {
        int c = ci * 256 + tid;
        float w[27];
        #pragma unroll
        for (int k = 0; k < 27; k++) w[k] = pw[(size_t)c * 27 + k];
        float acc[TT], xown[TT];
        #pragma unroll
        for (int t = 0; t < TT; t++) acc[t] = pb[c];
        #pragma unroll
        for (int di = 0; di < 3; di++) {
            int i2 = i + di - 1;
            if ((unsigned)i2 >= SS) continue;
            #pragma unroll
            for (int dj = 0; dj < 3; dj++) {
                int j2 = j + dj - 1;
                if ((unsigned)j2 >= SS) continue;
                int kidx = di * 3 + dj;
                const float* base = x + ((size_t)(1 + (i2 * SS + j2) * TT) * NB + n) * CC + c;
                bool cen = (di == 1 && dj == 1);
                #pragma unroll
                for (int t2 = 0; t2 < TT; t2++) {
                    float val = base[(size_t)t2 * NB * CC];
                    if (cen) xown[t2] = val;
                    if (t2 + 1 < TT) acc[t2 + 1] += w[kidx]      * val;
                    acc[t2]                      += w[9  + kidx] * val;
                    if (t2 > 0)      acc[t2 - 1] += w[18 + kidx] * val;
                }
            }
        }
        #pragma unroll
        for (int t = 0; t < TT; t++) {
            float v = xown[t] + acc[t];
            g_XBUF[((size_t)((1 + l * TT + t) * NB) + n) * CC + c] = v;
            rows[t][c] = v;
            s[t] += v; s2[t] += v * v;
        }
    }
    #pragma unroll
    for (int t = 0; t < TT; t++)
        for (int m = 16; m; m >>= 1) {
            s[t]  += __shfl_xor_sync(~0u, s[t],  m);
            s2[t] += __shfl_xor_sync(~0u, s2[t], m);
        }
    if (lane == 0) {
        #pragma unroll
        for (int t = 0; t < TT; t++) { reds[wid][t] = s[t]; reds2[wid][t] = s2[t]; }
    }
    __syncthreads();
    if (lane < 8) {
        float a = reds[lane][wid], a2 = reds2[lane][wid];
        #pragma unroll
        for (int m = 4; m; m >>= 1) {
            a  += __shfl_xor_sync(0xffu, a,  m);
            a2 += __shfl_xor_sync(0xffu, a2, m);
        }
        if (lane == 0) {
            float mean = a * (1.f / CC);
            float var  = a2 * (1.f / CC) - mean * mean;
            stat[wid][0] = mean;
            stat[wid][1] = rsqrtf(var + 1e-5f);
        }
    }
    __syncthreads();
    for (int ci = 0; ci < 4; ci++) {
        int c = ci * 256 + tid;
        float gc = g[c], bc = b[c];
        #pragma unroll
        for (int t = 0; t < TT; t++) {
            float v = rows[t][c];
            g_LNh[((size_t)((l * TT + t) * NB) + n) * CC + c] =
                __float2half_rn((v - stat[t][0]) * stat[t][1] * gc + bc);
        }
    }
}

// ---------------- LayerNorm (mode 1: spatial gather) -> fp16 ---------------
__global__ void ln_kernel(const float* __restrict__ src,
                          const float* __restrict__ srcCls,
                          __half* __restrict__ dst,
                          const float* __restrict__ g, const float* __restrict__ b,
                          int mode, int srcOff) {
    int row = blockIdx.x;
    const float* xr;
    if (mode == 0) {
        xr = src + (size_t)(row + srcOff) * CC;
    } else {
        int ls = row / SB, bb = row % SB;
        int t = bb / NB, n = bb % NB;
        if (ls == 0) xr = srcCls + (size_t)n * CC;
        else         xr = src + (size_t)(((ls - 1) * TT + t) * NB + n) * CC;
    }
    int tid = threadIdx.x;
    float s = 0.f, s2 = 0.f;
    float v[4];
    #pragma unroll
    for (int it = 0; it < 4; it++) {
        float val = xr[tid + it * 256];
        v[it] = val; s += val; s2 += val * val;
    }
    __shared__ float red[2][8];
    for (int m = 16; m; m >>= 1) {
        s  += __shfl_xor_sync(~0u, s, m);
        s2 += __shfl_xor_sync(~0u, s2, m);
    }
    if ((tid & 31) == 0) { red[0][tid >> 5] = s; red[1][tid >> 5] = s2; }
    __syncthreads();
    s = 0.f; s2 = 0.f;
    #pragma unroll
    for (int w = 0; w < 8; w++) { s += red[0][w]; s2 += red[1][w]; }
    float mean = s * (1.f / CC);
    float var  = s2 * (1.f / CC) - mean * mean;
    float inv  = rsqrtf(var + 1e-5f);
    __half* dr = dst + (size_t)row * CC;
    #pragma unroll
    for (int it = 0; it < 4; it++) {
        int c = tid + it * 256;
        dr[c] = __float2half_rn((v[it] - mean) * inv * g[c] + b[c]);
    }
}

// ---------------- fused spatial residual + LayerNorm2 ----------------------
__global__ void resid_ln_kernel(const float* __restrict__ g,
                                const float* __restrict__ b) {
    int row = blockIdx.x, tid = threadIdx.x;
    int token = row >> 3, n = row & 7;
    float v[4];
    float s = 0.f, s2 = 0.f;
    #pragma unroll
    for (int it = 0; it < 4; it++) {
        int c = tid + it * 256;
        float base = g_XBUF[(size_t)row * CC + c];
        float add;
        if (token == 0) {
            float a = 0.f;
            #pragma unroll
            for (int t = 0; t < TT; t++)
                a += g_PROJ[((size_t)(t * NB + n)) * CC + c];
            add = a * 0.125f;
        } else {
            int p = token - 1;
            int l = p >> 3, t = p & 7;
            add = g_PROJ[((size_t)((l + 1) * SB + t * NB + n)) * CC + c];
        }
        float vv = base + add;
        g_XBUF[(size_t)row * CC + c] = vv;
        v[it] = vv; s += vv; s2 += vv * vv;
    }
    __shared__ float red[2][8];
    for (int m = 16; m; m >>= 1) {
        s  += __shfl_xor_sync(~0u, s, m);
        s2 += __shfl_xor_sync(~0u, s2, m);
    }
    if ((tid & 31) == 0) { red[0][tid >> 5] = s; red[1][tid >> 5] = s2; }
    __syncthreads();
    s = 0.f; s2 = 0.f;
    #pragma unroll
    for (int w = 0; w < 8; w++) { s += red[0][w]; s2 += red[1][w]; }
    float mean = s * (1.f / CC);
    float var  = s2 * (1.f / CC) - mean * mean;
    float inv  = rsqrtf(var + 1e-5f);
    __half* dr = g_LNh + (size_t)row * CC;
    #pragma unroll
    for (int it = 0; it < 4; it++) {
        int c = tid + it * 256;
        dr[c] = __float2half_rn((v[it] - mean) * inv * g[c] + b[c]);
    }
}

// ---------------- fp16 tensor-core GEMM, cp.async + ldmatrix ---------------
// C[M,N] = A[M,K] @ B[N,K]^T + bias (+epilogue). Strided rows, batched.
// MODE 0: fp32 store | 1: QuickGELU->fp16 | 2: residual add fp32 | 3: fp16 store
// BATCH 0: none | 1: qkv-layout A/B (scores), S-out | 2: P/Vt in, qkv-scatter out
#define HSTR 40
#define STAGE_HALF (2 * 128 * HSTR)
#define GSTAGES 4
#define GSMEM_BYTES (GSTAGES * STAGE_HALF * 2)  // 81920

template<int MODE, int BATCH>
__global__ void __launch_bounds__(256, 2)
tgemm_kernel(const __half* __restrict__ A, size_t strideA,
             const __half* __restrict__ B, size_t strideB,
             const float* __restrict__ bias, const float* __restrict__ res,
             void* __restrict__ outv, size_t outStride,
             int M, int N, int K, int colLim) {
    extern __shared__ __half smh[];
    const int tid  = threadIdx.x;
    const int bm   = blockIdx.y * 128, bn = blockIdx.x * 128;
    const int z    = blockIdx.z;
    const int lane = tid & 31, wid = tid >> 5;
    const int wm   = (wid & 1) << 6;
    const int wn   = (wid >> 1) << 5;

    size_t aoff = 0, boff = 0, ooff = 0;
    if (BATCH == 1) {
        size_t e = (size_t)(z >> 4) * 3072 + (size_t)(z & 15) * 64;
        aoff = e; boff = e;
        ooff = (size_t)z * LS * SKP;
    } else if (BATCH == 2) {
        aoff = (size_t)z * LS * PKP;
        boff = (size_t)z * HD * PKP;
        ooff = (size_t)(z >> 4) * 1024 + (size_t)(z & 15) * 64;
    }

    const int  lrow  = tid & 127;
    const bool loadA = tid < 128;
    int  growi = loadA ? (bm + lrow) : (bn + lrow);
    const bool valid = loadA ? (growi < M) : (growi < N);
    const int  vsz   = valid ? 16 : 0;
    if (!valid) growi = 0;
    const __half* gRow = (loadA ? (A + aoff) : (B + boff))
                       + (size_t)growi * (loadA ? strideA : strideB);
    unsigned sbase = (unsigned)__cvta_generic_to_shared(smh);
    const unsigned dRowOff = (loadA ? 0 : 128 * HSTR * 2) + lrow * (HSTR * 2);

    // ldmatrix per-lane byte offsets (within a stage)
    // A x4 (fixed mt): matrices (mlo,klo),(mhi,klo),(mlo,khi),(mhi,khi)
    //   row = wm + mt*16 + (lane&15), col = ((lane>>4)<<3)
    // B x4 (pair p): matrices (n=2p tile,klo),(2p,khi),(2p+1,klo),(2p+1,khi)
    //   row = 128 + wn + (2p + (lane>>4))*8 + (lane&7), col = (((lane>>3)&1)<<3)
    unsigned aoff_lm[4], boff_lm[2];
    #pragma unroll
    for (int mt = 0; mt < 4; mt++)
        aoff_lm[mt] = (unsigned)(((wm + mt * 16 + (lane & 15)) * HSTR
                                  + ((lane >> 4) << 3)) * 2);
    #pragma unroll
    for (int p = 0; p < 2; p++)
        boff_lm[p] = (unsigned)(((128 + wn + (2 * p + (lane >> 4)) * 8 + (lane & 7)) * HSTR
                                 + (((lane >> 3) & 1) << 3)) * 2);

    float acc[16][4];
    #pragma unroll
    for (int i = 0; i < 16; i++)
        #pragma unroll
        for (int j = 0; j < 4; j++) acc[i][j] = 0.f;

    const int NS = K >> 5;

    #pragma unroll
    for (int s = 0; s < GSTAGES - 1; s++) {
        if (s < NS) {
            unsigned d = sbase + (unsigned)(s * STAGE_HALF * 2) + dRowOff;
            const __half* gp = gRow + s * 32;
            #pragma unroll
            for (int c = 0; c < 4; c++)
                asm volatile("cp.async.cg.shared.global [%0], [%1], 16, %2;\n"
                             :: "r"(d + c * 16), "l"(gp + c * 8), "r"(vsz));
        }
        asm volatile("cp.async.commit_group;\n");
    }

    for (int s = 0; s < NS; s++) {
        asm volatile("cp.async.wait_group %0;\n" :: "n"(GSTAGES - 2));
        __syncthreads();

        if (s + GSTAGES - 1 < NS) {
            int st = (s + GSTAGES - 1) & (GSTAGES - 1);
            unsigned d = sbase + (unsigned)(st * STAGE_HALF * 2) + dRowOff;
            const __half* gp = gRow + (s + GSTAGES - 1) * 32;
            #pragma unroll
            for (int c = 0; c < 4; c++)
                asm volatile("cp.async.cg.shared.global [%0], [%1], 16, %2;\n"
                             :: "r"(d + c * 16), "l"(gp + c * 8), "r"(vsz));
        }
        asm volatile("cp.async.commit_group;\n");

        const unsigned stb = sbase + (unsigned)((s & (GSTAGES - 1)) * STAGE_HALF * 2);

        #pragma unroll
        for (int kk = 0; kk < 32; kk += 16) {
            unsigned af[4][4], bf[4][2];
            #pragma unroll
            for (int mt = 0; mt < 4; mt++) {
                asm volatile(
                    "ldmatrix.sync.aligned.m8n8.x4.shared.b16 {%0,%1,%2,%3}, [%4];"
                    : "=r"(af[mt][0]), "=r"(af[mt][1]), "=r"(af[mt][2]), "=r"(af[mt][3])
                    : "r"(stb + aoff_lm[mt] + kk * 2));
            }
            #pragma unroll
            for (int p = 0; p < 2; p++) {
                asm volatile(
                    "ldmatrix.sync.aligned.m8n8.x4.shared.b16 {%0,%1,%2,%3}, [%4];"
                    : "=r"(bf[2*p][0]), "=r"(bf[2*p][1]),
                      "=r"(bf[2*p+1][0]), "=r"(bf[2*p+1][1])
                    : "r"(stb + boff_lm[p] + kk * 2));
            }
            #pragma unroll
            for (int mt = 0; mt < 4; mt++)
                #pragma unroll
                for (int nt = 0; nt < 4; nt++) {
                    float* c = acc[mt * 4 + nt];
                    asm volatile(
                        "mma.sync.aligned.m16n8k16.row.col.f32.f16.f16.f32 "
                        "{%0,%1,%2,%3}, {%4,%5,%6,%7}, {%8,%9}, {%0,%1,%2,%3};\n"
                        : "+f"(c[0]), "+f"(c[1]), "+f"(c[2]), "+f"(c[3])
                        : "r"(af[mt][0]), "r"(af[mt][1]), "r"(af[mt][2]), "r"(af[mt][3]),
                          "r"(bf[nt][0]), "r"(bf[nt][1]));
                }
        }
    }

    float*   outF = (float*)outv;
    __half2* outH = (__half2*)outv;
    const int erow = lane >> 2;
    const int ecol = (lane & 3) * 2;
    #pragma unroll
    for (int mt = 0; mt < 4; mt++) {
        #pragma unroll
        for (int nt = 0; nt < 4; nt++) {
            const float* c = acc[mt * 4 + nt];
            int col = bn + wn + nt * 8 + ecol;
            if (col >= colLim) continue;
            float bv0 = bias[col], bv1 = bias[col + 1];
            #pragma unroll
            for (int half = 0; half < 2; half++) {
                int row = bm + wm + mt * 16 + erow + half * 8;
                if (row < M) {
                    size_t off = ooff + (size_t)row * outStride + col;
                    float v0 = c[half * 2 + 0] + bv0;
                    float v1 = c[half * 2 + 1] + bv1;
                    if (MODE == 1) {
                        v0 = v0 / (1.f + expf(-1.702f * v0));
                        v1 = v1 / (1.f + expf(-1.702f * v1));
                        outH[off >> 1] = __floats2half2_rn(v0, v1);
                    } else if (MODE == 3) {
                        outH[off >> 1] = __floats2half2_rn(v0, v1);
                    } else {
                        if (MODE == 2) {
                            v0 += res[off];
                            v1 += res[off + 1];
                        }
                        outF[off]     = v0;
                        outF[off + 1] = v1;
                    }
                }
            }
        }
    }
}

// ---------------- spatial softmax: scale + rel-pos bias + normalize --------
__global__ void softmax_kernel(const float* __restrict__ rpb_s) {
    int wid = threadIdx.x >> 5, lane = threadIdx.x & 31;
    int q = blockIdx.x * 4 + wid;
    if (q >= LS) return;
    int b = blockIdx.y, h = blockIdx.z;
    size_t sbase = ((size_t)(b * 16 + h) * LS + q) * SKP;
    size_t pbase = ((size_t)(b * 16 + h) * LS + q) * PKP;
    int qi = 0, qj = 0;
    if (q > 0) { qi = (q - 1) / SS; qj = (q - 1) % SS; }
    float sv[7];
    float mx = -1e30f;
    #pragma unroll
    for (int it = 0; it < 7; it++) {
        int k = lane + it * 32;
        float s = -1e30f;
        if (k < LS) {
            s = g_S[sbase + k] * 0.125f;
            if (q > 0 && k > 0) {
                int ki = (k - 1) / SS, kj = (k - 1) % SS;
                int idx = (qi - ki + SS - 1) * (2 * SS - 1) + (qj - kj + SS - 1);
                s += rpb_s[idx * NH + h];
            }
        }
        sv[it] = s;
        mx = fmaxf(mx, s);
    }
    for (int m = 16; m; m >>= 1) mx = fmaxf(mx, __shfl_xor_sync(~0u, mx, m));
    float sum = 0.f;
    #pragma unroll
    for (int it = 0; it < 7; it++) {
        float p = (sv[it] > -1e29f) ? expf(sv[it] - mx) : 0.f;
        sv[it] = p; sum += p;
    }
    for (int m = 16; m; m >>= 1) sum += __shfl_xor_sync(~0u, sum, m);
    float inv = 1.f / sum;
    #pragma unroll
    for (int it = 0; it < 7; it++) {
        int k = lane + it * 32;
        if (k < LS) g_P[pbase + k] = __float2half_rn(sv[it] * inv);
    }
    if (lane < PKP - LS) g_P[pbase + LS + lane] = __ushort_as_half(0);
}

// ---------------- V transpose: Vt[bh][d][key] fp16, key-padded -------------
__global__ void vt_kernel() {
    __shared__ unsigned vsm[LS * 33];
    int z = blockIdx.x;
    int b = z >> 4, h = z & 15;
    int tid = threadIdx.x;
    for (int idx = tid; idx < LS * 32; idx += 256) {
        int ls = idx >> 5, dp = idx & 31;
        vsm[ls * 33 + dp] = *(const unsigned*)
            (g_QKVh + ((size_t)(ls * SB + b)) * 3072 + 2048 + h * 64 + dp * 2);
    }
    __syncthreads();
    const __half* vh = (const __half*)vsm;
    __half2* dst = (__half2*)(g_Vt + (size_t)z * HD * PKP);
    for (int idx = tid; idx < HD * (PKP / 2); idx += 256) {
        int d = idx / (PKP / 2), kp = idx % (PKP / 2);
        __half h0 = (2 * kp     < LS) ? vh[(2 * kp)     * 66 + d] : __ushort_as_half(0);
        __half h1 = (2 * kp + 1 < LS) ? vh[(2 * kp + 1) * 66 + d] : __ushort_as_half(0);
        dst[(size_t)d * (PKP / 2) + kp] = __halves2half2(h0, h1);
    }
}

// ---------------- Temporal attention: batch (n,l), seq T=8 -----------------
__global__ void temporal_attn_kernel(const float* __restrict__ rpb_t) {
    int bid = blockIdx.x;
    int h = bid & 15;
    int nl = bid >> 4;
    int n = nl & 7;
    int l = nl >> 3;
    __shared__ float Q[TT][HD + 1], K[TT][HD + 1], V[TT][HD + 1], P[TT][TT];
    int d = threadIdx.x;
    #pragma unroll
    for (int t = 0; t < TT; t++) {
        size_t r = (size_t)((l * TT + t) * NB + n);
        const __half* q = g_QKVh + r * 3072 + h * HD + d;
        Q[t][d] = __half2float(q[0]) * 0.125f;
        K[t][d] = __half2float(q[1024]);
        V[t][d] = __half2float(q[2048]);
    }
    __syncthreads();
    int tq = d >> 3, tk = d & 7;
    float s = rpb_t[(tq - tk + TT - 1) * NH + h];
    #pragma unroll
    for (int k = 0; k < HD; k++) s += Q[tq][k] * K[tk][k];
    float m = s;
    for (int msk = 4; msk; msk >>= 1) m = fmaxf(m, __shfl_xor_sync(~0u, m, msk));
    float p = expf(s - m);
    float sum = p;
    for (int msk = 4; msk; msk >>= 1) sum += __shfl_xor_sync(~0u, sum, msk);
    P[tq][tk] = p / sum;
    __syncthreads();
    #pragma unroll
    for (int t = 0; t < TT; t++) {
        float o = 0.f;
        #pragma unroll
        for (int k = 0; k < TT; k++) o += P[t][k] * V[k][d];
        g_ATTh[((size_t)((l * TT + t) * NB + n)) * CC + h * HD + d] = __float2half_rn(o);
    }
}

// ---------------------------------------------------------------------------
extern "C" void kernel_launch(void* const* d_in, const int* in_sizes, int n_in,
                              void* d_out, int out_size) {
    const float* x      = (const float*)d_in[0];
    const float* pos_w  = (const float*)d_in[1];
    const float* pos_b  = (const float*)d_in[2];
    const float* ln_t_g = (const float*)d_in[3];
    const float* ln_t_b = (const float*)d_in[4];
    const float* rpb_t  = (const float*)d_in[5];
    const float* wqkv_t = (const float*)d_in[6];
    const float* bqkv_t = (const float*)d_in[7];
    const float* wo_t   = (const float*)d_in[8];
    const float* bo_t   = (const float*)d_in[9];
    const float* ln1_g  = (const float*)d_in[10];
    const float* ln1_b  = (const float*)d_in[11];
    const float* rpb_s  = (const float*)d_in[12];
    const float* wqkv_s = (const float*)d_in[13];
    const float* bqkv_s = (const float*)d_in[14];
    const float* wo_s   = (const float*)d_in[15];
    const float* bo_s   = (const float*)d_in[16];
    const float* ln2_g  = (const float*)d_in[17];
    const float* ln2_b  = (const float*)d_in[18];
    const float* fc_w   = (const float*)d_in[19];
    const float* fc_b   = (const float*)d_in[20];
    const float* proj_w = (const float*)d_in[21];
    const float* proj_b = (const float*)d_in[22];
    float* out = (float*)d_out;

    float *pX, *pPROJ, *pXT, *pS, *pZERO;
    __half *pLNh, *pQKVh, *pATTh, *pHh, *pWTh, *pP, *pVt;
    cudaGetSymbolAddress((void**)&pX,    g_XBUF);
    cudaGetSymbolAddress((void**)&pLNh,  g_LNh);
    cudaGetSymbolAddress((void**)&pQKVh, g_QKVh);
    cudaGetSymbolAddress((void**)&pATTh, g_ATTh);
    cudaGetSymbolAddress((void**)&pPROJ, g_PROJ);
    cudaGetSymbolAddress((void**)&pXT,   g_XT);
    cudaGetSymbolAddress((void**)&pHh,   g_Hh);
    cudaGetSymbolAddress((void**)&pWTh,  g_WTh);
    cudaGetSymbolAddress((void**)&pS,    g_S);
    cudaGetSymbolAddress((void**)&pP,    g_P);
    cudaGetSymbolAddress((void**)&pVt,   g_Vt);
    cudaGetSymbolAddress((void**)&pZERO, g_ZERO);

    #define SET_SMEM(k) cudaFuncSetAttribute(k, \
        cudaFuncAttributeMaxDynamicSharedMemorySize, GSMEM_BYTES)
    SET_SMEM((tgemm_kernel<0,0>)); SET_SMEM((tgemm_kernel<1,0>));
    SET_SMEM((tgemm_kernel<2,0>)); SET_SMEM((tgemm_kernel<3,0>));
    SET_SMEM((tgemm_kernel<0,1>)); SET_SMEM((tgemm_kernel<3,2>));

    // fp16 weight copies (contiguous arena; one merged prep launch)
    __half* wqkvT = pWTh;
    __half* woT   = pWTh + 3145728;
    __half* wqkvS = pWTh + 4194304;
    __half* woS   = pWTh + 7340032;
    __half* fcW   = pWTh + 8388608;
    __half* projW = pWTh + 12582912;
    W6 ws;
    ws.p[0] = wqkv_t; ws.p[1] = wo_t; ws.p[2] = wqkv_s;
    ws.p[3] = wo_s;   ws.p[4] = fc_w; ws.p[5] = proj_w;
    wprep_all_kernel<<<16384, 256>>>(ws, pWTh);

    // Stage 1+LN_t fused: conv pos embed -> XBUF, LN_t -> LNh
    pos_ln_kernel<<<dim3(LL, NB), 256>>>(x, pos_w, pos_b, ln_t_g, ln_t_b);

    // Stage 2: temporal attention on patch rows -> xt_full (fp32) in pXT
    tgemm_kernel<3,0><<<dim3(24, 98, 1), 256, GSMEM_BYTES>>>(
        pLNh, 1024, wqkvT, 1024, bqkv_t, nullptr, pQKVh, 3072,
        PROWS, 3072, 1024, 3072);
    temporal_attn_kernel<<<LL * NB * NH, 64>>>(rpb_t);
    tgemm_kernel<2,0><<<dim3(8, 98, 1), 256, GSMEM_BYTES>>>(
        pATTh, 1024, woT, 1024, bo_t, pX + (size_t)NB * CC, pXT, 1024,
        PROWS, 1024, 1024, 1024);

    // Stage 3: spatial attention (seq 197 incl. cls) via batched GEMMs
    ln_kernel<<<SROWS, 256>>>(pXT, pX, pLNh, ln1_g, ln1_b, 1, 0);
    tgemm_kernel<3,0><<<dim3(24, 99, 1), 256, GSMEM_BYTES>>>(
        pLNh, 1024, wqkvS, 1024, bqkv_s, nullptr, pQKVh, 3072,
        SROWS, 3072, 1024, 3072);
    tgemm_kernel<0,1><<<dim3(2, 2, BH), 256, GSMEM_BYTES>>>(
        pQKVh, (size_t)SB * 3072, pQKVh + 1024, (size_t)SB * 3072,
        pZERO, nullptr, pS, SKP, LS, LS, 64, 198);
    softmax_kernel<<<dim3((LS + 3) / 4, SB, NH), 128>>>(rpb_s);
    vt_kernel<<<BH, 256>>>();
    tgemm_kernel<3,2><<<dim3(1, 2, BH), 256, GSMEM_BYTES>>>(
        pP, PKP, pVt, PKP, pZERO, nullptr, pATTh, (size_t)SB * 1024,
        LS, HD, PKP, HD);
    tgemm_kernel<0,0><<<dim3(8, 99, 1), 256, GSMEM_BYTES>>>(
        pATTh, 1024, woS, 1024, bo_s, nullptr, pPROJ, 1024,
        SROWS, 1024, 1024, 1024);

    // fused: spatial residual (+cls mean) into XBUF, then LN2 -> LNh
    resid_ln_kernel<<<ROWS, 256>>>(ln2_g, ln2_b);

    // Stage 4: MLP with QuickGELU (hidden in fp16)
    tgemm_kernel<1,0><<<dim3(32, 99, 1), 256, GSMEM_BYTES>>>(
        pLNh, 1024, fcW, 1024, fc_b, nullptr, pHh, 4096,
        ROWS, 4096, 1024, 4096);
    tgemm_kernel<2,0><<<dim3(8, 99, 1), 256, GSMEM_BYTES>>>(
        pHh, 4096, projW, 4096, proj_b, pX, out, 1024,
        ROWS, 1024, 4096, 1024);
}